// round 2
// baseline (speedup 1.0000x reference)
#include <cuda_runtime.h>
#include <math_constants.h>
#include <cstdint>

#define BDIM 8192
#define DDIM 512
#define MARGIN 0.2f

// ---------------- scratch (device globals: allocation-free) ----------------
__device__ float g_dist[(size_t)BDIM * BDIM];   // 256 MB distance matrix
__device__ float g_sq[BDIM];                    // squared norms
__device__ int   g_hp_bits[BDIM];               // hardest positive (float bits, atomicMax)
__device__ float g_loss[BDIM];                  // per-row loss (deterministic)

// ---------------- init: hardest_pos = -inf ----------------
__global__ void init_hp() {
    int i = blockIdx.x * blockDim.x + threadIdx.x;
    if (i < BDIM) g_hp_bits[i] = 0xFF800000; // -inf bits
}

// ---------------- squared norms: one block (128 thr) per row ----------------
__global__ void __launch_bounds__(128) sqnorm_kernel(const float* __restrict__ emb) {
    const int i = blockIdx.x;
    const int tid = threadIdx.x;
    float4 v = ((const float4*)(emb + (size_t)i * DDIM))[tid]; // 128*4 = 512
    float s = v.x * v.x + v.y * v.y + v.z * v.z + v.w * v.w;
    #pragma unroll
    for (int o = 16; o > 0; o >>= 1) s += __shfl_down_sync(0xFFFFFFFF, s, o);
    __shared__ float ws[4];
    if ((tid & 31) == 0) ws[tid >> 5] = s;
    __syncthreads();
    if (tid == 0) g_sq[i] = ws[0] + ws[1] + ws[2] + ws[3];
}

// ---------------- GEMM + distance epilogue ----------------
// C = E * E^T, 128x128 tile per block, 256 threads, 8x8 per thread, BK=8.
__global__ void __launch_bounds__(256) gemm_dist(const float* __restrict__ emb,
                                                 const int* __restrict__ labels) {
    __shared__ float As[8][128];
    __shared__ float Bs[8][128];

    const int tid = threadIdx.x;
    const int tx = tid & 15;        // 0..15 -> col group
    const int ty = tid >> 4;        // 0..15 -> row group
    const int rowBase = blockIdx.y * 128;
    const int colBase = blockIdx.x * 128;

    float c[8][8];
    #pragma unroll
    for (int i = 0; i < 8; i++)
        #pragma unroll
        for (int j = 0; j < 8; j++) c[i][j] = 0.f;

    const int lrow = tid >> 1;       // 0..127
    const int lk   = (tid & 1) * 4;  // 0 or 4
    const float* Aptr = emb + (size_t)(rowBase + lrow) * DDIM + lk;
    const float* Bptr = emb + (size_t)(colBase + lrow) * DDIM + lk;

    for (int k0 = 0; k0 < DDIM; k0 += 8) {
        float4 av = *(const float4*)(Aptr + k0);
        float4 bv = *(const float4*)(Bptr + k0);
        __syncthreads();
        As[lk + 0][lrow] = av.x; As[lk + 1][lrow] = av.y;
        As[lk + 2][lrow] = av.z; As[lk + 3][lrow] = av.w;
        Bs[lk + 0][lrow] = bv.x; Bs[lk + 1][lrow] = bv.y;
        Bs[lk + 2][lrow] = bv.z; Bs[lk + 3][lrow] = bv.w;
        __syncthreads();
        #pragma unroll
        for (int k = 0; k < 8; k++) {
            float4 a0 = *(const float4*)&As[k][ty * 8];
            float4 a1 = *(const float4*)&As[k][ty * 8 + 4];
            float4 b0 = *(const float4*)&Bs[k][tx * 8];
            float4 b1 = *(const float4*)&Bs[k][tx * 8 + 4];
            float a[8] = {a0.x, a0.y, a0.z, a0.w, a1.x, a1.y, a1.z, a1.w};
            float b[8] = {b0.x, b0.y, b0.z, b0.w, b1.x, b1.y, b1.z, b1.w};
            #pragma unroll
            for (int i = 0; i < 8; i++)
                #pragma unroll
                for (int j = 0; j < 8; j++)
                    c[i][j] = fmaf(a[i], b[j], c[i][j]);
        }
    }

    // Epilogue: d2 = sq_i + sq_j - 2*dot; diag -> 0; dist = sqrt; store; update hardest_pos.
    #pragma unroll
    for (int i = 0; i < 8; i++) {
        const int gi = rowBase + ty * 8 + i;
        const float sqi = g_sq[gi];
        const int li = labels[gi];
        float out[8];
        #pragma unroll
        for (int j = 0; j < 8; j++) {
            const int gj = colBase + tx * 8 + j;
            float d2 = sqi + g_sq[gj] - 2.f * c[i][j];
            if (gi == gj) d2 = 0.f;
            d2 = fmaxf(d2, 0.f);
            const float dist = (d2 > 0.f) ? sqrtf(d2) : 0.f;
            out[j] = dist;
            if (d2 > 0.f && labels[gj] == li)
                atomicMax(&g_hp_bits[gi], __float_as_int(dist)); // valid: updates >= 0, init -inf
        }
        float4* dst = (float4*)&g_dist[(size_t)gi * BDIM + colBase + tx * 8];
        dst[0] = make_float4(out[0], out[1], out[2], out[3]);
        dst[1] = make_float4(out[4], out[5], out[6], out[7]);
    }
}

// ---------------- row pass: semi-hard negative selection ----------------
__global__ void __launch_bounds__(256) rowpass(const int* __restrict__ labels) {
    const int i = blockIdx.x;
    const int tid = threadIdx.x;
    const float hp = __int_as_float(g_hp_bits[i]);
    const int li = labels[i];

    float hn_semi = CUDART_INF_F;
    float hn_all  = CUDART_INF_F;
    int any = 0;

    const float4* drow = (const float4*)&g_dist[(size_t)i * BDIM];
    const int4*   lrow = (const int4*)labels;

    for (int v = tid; v < BDIM / 4; v += 256) {
        const float4 d = drow[v];
        const int4 l = lrow[v];
        if (l.x != li) { hn_all = fminf(hn_all, d.x); if (d.x > hp) { any = 1; hn_semi = fminf(hn_semi, d.x); } }
        if (l.y != li) { hn_all = fminf(hn_all, d.y); if (d.y > hp) { any = 1; hn_semi = fminf(hn_semi, d.y); } }
        if (l.z != li) { hn_all = fminf(hn_all, d.z); if (d.z > hp) { any = 1; hn_semi = fminf(hn_semi, d.z); } }
        if (l.w != li) { hn_all = fminf(hn_all, d.w); if (d.w > hp) { any = 1; hn_semi = fminf(hn_semi, d.w); } }
    }

    __shared__ float ss[256], sa[256];
    __shared__ int sy[256];
    ss[tid] = hn_semi; sa[tid] = hn_all; sy[tid] = any;
    __syncthreads();
    #pragma unroll
    for (int s = 128; s > 0; s >>= 1) {
        if (tid < s) {
            ss[tid] = fminf(ss[tid], ss[tid + s]);
            sa[tid] = fminf(sa[tid], sa[tid + s]);
            sy[tid] |= sy[tid + s];
        }
        __syncthreads();
    }
    if (tid == 0) {
        const float hn = sy[0] ? ss[0] : sa[0];
        const float loss = hp - hn + MARGIN;   // -inf arithmetic -> relu gives 0
        g_loss[i] = (loss > 0.f) ? loss : 0.f;
    }
}

// ---------------- deterministic final mean ----------------
__global__ void __launch_bounds__(256) final_reduce(float* __restrict__ out) {
    const int tid = threadIdx.x;
    float acc = 0.f;
    for (int k = tid; k < BDIM; k += 256) acc += g_loss[k];
    __shared__ float s[256];
    s[tid] = acc;
    __syncthreads();
    #pragma unroll
    for (int st = 128; st > 0; st >>= 1) {
        if (tid < st) s[tid] += s[tid + st];
        __syncthreads();
    }
    if (tid == 0) out[0] = s[0] / (float)BDIM;
}

// ---------------- launch ----------------
extern "C" void kernel_launch(void* const* d_in, const int* in_sizes, int n_in,
                              void* d_out, int out_size) {
    const float* emb = (const float*)d_in[0];
    const int* labels = (const int*)d_in[1];
    float* out = (float*)d_out;

    init_hp<<<(BDIM + 255) / 256, 256>>>();
    sqnorm_kernel<<<BDIM, 128>>>(emb);
    dim3 grid(BDIM / 128, BDIM / 128);
    gemm_dist<<<grid, 256>>>(emb, labels);
    rowpass<<<BDIM, 256>>>(labels);
    final_reduce<<<1, 256>>>(out);
}

// round 3
// speedup vs baseline: 1.9559x; 1.9559x over previous
#include <cuda_runtime.h>
#include <math_constants.h>
#include <cstdint>

#define BDIM 8192
#define DDIM 512
#define MARGIN 0.2f
#define TILES 64                 // 8192 / 128
#define NTRI  (TILES * (TILES + 1) / 2)   // 2080 upper-triangle tiles

// ---------------- scratch (device globals: allocation-free) ----------------
__device__ float g_sq[BDIM];                     // squared norms
__device__ float g_hp2[BDIM];                    // hardest positive squared dist (-inf if none)
__device__ float g_all2[TILES * BDIM];           // per (tile, row) min d2 over negatives
__device__ float g_semi2[TILES * BDIM];          // per (tile, row) min d2 over semi-hard negatives
__device__ float g_loss[BDIM];                   // per-row loss
__device__ int   g_ccnt[512];                    // class member counts
__device__ int   g_cidx[512 * BDIM];             // class member lists

// ---------------- zero class counts ----------------
__global__ void init_cnt() {
    int i = blockIdx.x * blockDim.x + threadIdx.x;
    if (i < 512) g_ccnt[i] = 0;
}

// ---------------- squared norms: one block (128 thr) per row ----------------
__global__ void __launch_bounds__(128) sqnorm_kernel(const float* __restrict__ emb) {
    const int i = blockIdx.x;
    const int tid = threadIdx.x;
    float4 v = ((const float4*)(emb + (size_t)i * DDIM))[tid];
    float s = v.x * v.x + v.y * v.y + v.z * v.z + v.w * v.w;
    #pragma unroll
    for (int o = 16; o > 0; o >>= 1) s += __shfl_down_sync(0xFFFFFFFF, s, o);
    __shared__ float ws[4];
    if ((tid & 31) == 0) ws[tid >> 5] = s;
    __syncthreads();
    if (tid == 0) g_sq[i] = ws[0] + ws[1] + ws[2] + ws[3];
}

// ---------------- scatter indices into class buckets ----------------
__global__ void scatter_cls(const int* __restrict__ labels) {
    int i = blockIdx.x * blockDim.x + threadIdx.x;
    if (i < BDIM) {
        int c = labels[i];
        int s = atomicAdd(&g_ccnt[c], 1);
        g_cidx[c * BDIM + s] = i;
    }
}

// ---------------- hardest positive (squared): one warp per anchor ----------------
__global__ void __launch_bounds__(256) hp_kernel(const float* __restrict__ emb,
                                                 const int* __restrict__ labels) {
    const int w = blockIdx.x * 8 + (threadIdx.x >> 5);   // anchor index
    const int lane = threadIdx.x & 31;
    const float4* e4 = (const float4*)emb;

    float4 a[4];
    #pragma unroll
    for (int k = 0; k < 4; k++) a[k] = e4[(size_t)w * 128 + k * 32 + lane];

    const float sqi = g_sq[w];
    const int c = labels[w];
    const int cnt = g_ccnt[c];
    float m2 = -CUDART_INF_F;

    for (int m = 0; m < cnt; m++) {
        const int j = g_cidx[c * BDIM + m];
        if (j == w) continue;
        float p = 0.f;
        #pragma unroll
        for (int k = 0; k < 4; k++) {
            float4 b = e4[(size_t)j * 128 + k * 32 + lane];
            p += a[k].x * b.x + a[k].y * b.y + a[k].z * b.z + a[k].w * b.w;
        }
        #pragma unroll
        for (int o = 16; o > 0; o >>= 1) p += __shfl_xor_sync(0xFFFFFFFF, p, o);
        const float d2 = sqi + g_sq[j] - 2.f * p;
        if (d2 > 0.f) m2 = fmaxf(m2, d2);
    }
    if (lane == 0) g_hp2[w] = m2;
}

// ---------------- GEMM (upper triangle) + fused negative-min epilogue ----------------
// C = E * E^T, 128x128 tile per block, 256 threads, 8x8 per thread, BK=8.
__global__ void __launch_bounds__(256) gemm_fused(const float* __restrict__ emb,
                                                  const int* __restrict__ labels) {
    __shared__ float As[8][128];
    __shared__ float Bs[8][128];
    __shared__ float red[128 * 17];   // reduction staging (padded, bank-conflict free)

    // decode triangular block index -> (by, bx), bx >= by
    int rem = blockIdx.x, by = 0;
    while (rem >= TILES - by) { rem -= TILES - by; by++; }
    const int bx = by + rem;

    const int tid = threadIdx.x;
    const int tx = tid & 15;
    const int ty = tid >> 4;
    const int rowBase = by * 128;
    const int colBase = bx * 128;

    float c[8][8];
    #pragma unroll
    for (int i = 0; i < 8; i++)
        #pragma unroll
        for (int j = 0; j < 8; j++) c[i][j] = 0.f;

    const int lrow = tid >> 1;
    const int lk   = (tid & 1) * 4;
    const float* Aptr = emb + (size_t)(rowBase + lrow) * DDIM + lk;
    const float* Bptr = emb + (size_t)(colBase + lrow) * DDIM + lk;

    for (int k0 = 0; k0 < DDIM; k0 += 8) {
        float4 av = *(const float4*)(Aptr + k0);
        float4 bv = *(const float4*)(Bptr + k0);
        __syncthreads();
        As[lk + 0][lrow] = av.x; As[lk + 1][lrow] = av.y;
        As[lk + 2][lrow] = av.z; As[lk + 3][lrow] = av.w;
        Bs[lk + 0][lrow] = bv.x; Bs[lk + 1][lrow] = bv.y;
        Bs[lk + 2][lrow] = bv.z; Bs[lk + 3][lrow] = bv.w;
        __syncthreads();
        #pragma unroll
        for (int k = 0; k < 8; k++) {
            float4 a0 = *(const float4*)&As[k][ty * 8];
            float4 a1 = *(const float4*)&As[k][ty * 8 + 4];
            float4 b0 = *(const float4*)&Bs[k][tx * 8];
            float4 b1 = *(const float4*)&Bs[k][tx * 8 + 4];
            float a[8] = {a0.x, a0.y, a0.z, a0.w, a1.x, a1.y, a1.z, a1.w};
            float b[8] = {b0.x, b0.y, b0.z, b0.w, b1.x, b1.y, b1.z, b1.w};
            #pragma unroll
            for (int i = 0; i < 8; i++)
                #pragma unroll
                for (int j = 0; j < 8; j++)
                    c[i][j] = fmaf(a[i], b[j], c[i][j]);
        }
    }

    // Per-thread epilogue state
    float sqi_v[8], hp2i[8], sqj_v[8], hp2j[8];
    int li_v[8], lj_v[8];
    #pragma unroll
    for (int i = 0; i < 8; i++) {
        const int gi = rowBase + ty * 8 + i;
        sqi_v[i] = g_sq[gi]; li_v[i] = labels[gi]; hp2i[i] = g_hp2[gi];
    }
    #pragma unroll
    for (int j = 0; j < 8; j++) {
        const int gj = colBase + tx * 8 + j;
        sqj_v[j] = g_sq[gj]; lj_v[j] = labels[gj]; hp2j[j] = g_hp2[gj];
    }

    float allr[8], semir[8], allc[8], semic[8];
    #pragma unroll
    for (int i = 0; i < 8; i++) {
        allr[i] = CUDART_INF_F; semir[i] = CUDART_INF_F;
        allc[i] = CUDART_INF_F; semic[i] = CUDART_INF_F;
    }

    #pragma unroll
    for (int i = 0; i < 8; i++) {
        #pragma unroll
        for (int j = 0; j < 8; j++) {
            const float d2 = sqi_v[i] + sqj_v[j] - 2.f * c[i][j];
            const float v = fmaxf(d2, 0.f);
            if (li_v[i] != lj_v[j]) {   // negative pair (diagonal auto-excluded: same label)
                allr[i] = fminf(allr[i], v);
                if (v > hp2i[i]) semir[i] = fminf(semir[i], v);
                allc[j] = fminf(allc[j], v);
                if (v > hp2j[j]) semic[j] = fminf(semic[j], v);
            }
        }
    }

    // Block-level min reductions: combine 16 threads per row/col, write one partial per row.
    // Row-side arrays -> slot (bx, rowBase+r); col-side -> slot (by, colBase+r) (skip if bx==by).
    {
        // row-side: group=ty, lane=tx
        #pragma unroll
        for (int pass = 0; pass < 2; pass++) {
            float* vals = pass ? semir : allr;
            float* out = pass ? g_semi2 : g_all2;
            __syncthreads();
            #pragma unroll
            for (int e = 0; e < 8; e++) red[(ty * 8 + e) * 17 + tx] = vals[e];
            __syncthreads();
            if (tid < 128) {
                float m = red[tid * 17];
                #pragma unroll
                for (int k = 1; k < 16; k++) m = fminf(m, red[tid * 17 + k]);
                out[(size_t)bx * BDIM + rowBase + tid] = m;
            }
        }
        // col-side: group=tx, lane=ty
        if (bx != by) {
            #pragma unroll
            for (int pass = 0; pass < 2; pass++) {
                float* vals = pass ? semic : allc;
                float* out = pass ? g_semi2 : g_all2;
                __syncthreads();
                #pragma unroll
                for (int e = 0; e < 8; e++) red[(tx * 8 + e) * 17 + ty] = vals[e];
                __syncthreads();
                if (tid < 128) {
                    float m = red[tid * 17];
                    #pragma unroll
                    for (int k = 1; k < 16; k++) m = fminf(m, red[tid * 17 + k]);
                    out[(size_t)by * BDIM + colBase + tid] = m;
                }
            }
        }
    }
}

// ---------------- per-row finish: combine 64 tile partials, compute loss ----------------
__global__ void __launch_bounds__(256) rowfinish() {
    const int r = blockIdx.x * 256 + threadIdx.x;   // grid covers all 8192 rows
    float mA = CUDART_INF_F, mS = CUDART_INF_F;
    #pragma unroll 8
    for (int t = 0; t < TILES; t++) {
        mA = fminf(mA, g_all2[(size_t)t * BDIM + r]);
        mS = fminf(mS, g_semi2[(size_t)t * BDIM + r]);
    }
    const float hn2 = (mS < CUDART_INF_F) ? mS : mA;
    const float hp2 = g_hp2[r];
    float loss = 0.f;
    if (hp2 >= 0.f) {
        const float l = sqrtf(hp2) - sqrtf(hn2) + MARGIN;
        loss = fmaxf(l, 0.f);
    }
    g_loss[r] = loss;
}

// ---------------- deterministic final mean ----------------
__global__ void __launch_bounds__(256) final_reduce(float* __restrict__ out) {
    const int tid = threadIdx.x;
    float acc = 0.f;
    for (int k = tid; k < BDIM; k += 256) acc += g_loss[k];
    __shared__ float s[256];
    s[tid] = acc;
    __syncthreads();
    #pragma unroll
    for (int st = 128; st > 0; st >>= 1) {
        if (tid < st) s[tid] += s[tid + st];
        __syncthreads();
    }
    if (tid == 0) out[0] = s[0] / (float)BDIM;
}

// ---------------- launch ----------------
extern "C" void kernel_launch(void* const* d_in, const int* in_sizes, int n_in,
                              void* d_out, int out_size) {
    const float* emb = (const float*)d_in[0];
    const int* labels = (const int*)d_in[1];
    float* out = (float*)d_out;

    init_cnt<<<2, 256>>>();
    sqnorm_kernel<<<BDIM, 128>>>(emb);
    scatter_cls<<<BDIM / 256, 256>>>(labels);
    hp_kernel<<<BDIM / 8, 256>>>(emb, labels);
    gemm_fused<<<NTRI, 256>>>(emb, labels);
    rowfinish<<<BDIM / 256, 256>>>();
    final_reduce<<<1, 256>>>(out);
}

// round 6
// speedup vs baseline: 4.3390x; 2.2184x over previous
#include <cuda_runtime.h>
#include <math_constants.h>
#include <cstdint>

#define BDIM 8192
#define DDIM 512
#define MARGIN 0.2f
#define TILES 64
#define NTRI  (TILES * (TILES + 1) / 2)

// ---------------- scratch ----------------
__device__ float g_sq[BDIM];
__device__ float g_hp2[BDIM];
__device__ float g_all2[TILES * BDIM];
__device__ float g_semi2[TILES * BDIM];
__device__ float g_loss[BDIM];
__device__ int   g_ccnt[512];
__device__ int   g_cidx[512 * BDIM];

// ---------------- small kernels ----------------
__global__ void init_cnt() {
    int i = blockIdx.x * blockDim.x + threadIdx.x;
    if (i < 512) g_ccnt[i] = 0;
}

__global__ void __launch_bounds__(128) sqnorm_kernel(const float* __restrict__ emb) {
    const int i = blockIdx.x;
    const int tid = threadIdx.x;
    float4 v = ((const float4*)(emb + (size_t)i * DDIM))[tid];
    float s = v.x * v.x + v.y * v.y + v.z * v.z + v.w * v.w;
    #pragma unroll
    for (int o = 16; o > 0; o >>= 1) s += __shfl_down_sync(0xFFFFFFFF, s, o);
    __shared__ float ws[4];
    if ((tid & 31) == 0) ws[tid >> 5] = s;
    __syncthreads();
    if (tid == 0) g_sq[i] = ws[0] + ws[1] + ws[2] + ws[3];
}

__global__ void scatter_cls(const int* __restrict__ labels) {
    int i = blockIdx.x * blockDim.x + threadIdx.x;
    if (i < BDIM) {
        int c = labels[i];
        int s = atomicAdd(&g_ccnt[c], 1);
        g_cidx[c * BDIM + s] = i;
    }
}

__global__ void __launch_bounds__(256) hp_kernel(const float* __restrict__ emb,
                                                 const int* __restrict__ labels) {
    const int w = blockIdx.x * 8 + (threadIdx.x >> 5);
    const int lane = threadIdx.x & 31;
    const float4* e4 = (const float4*)emb;
    float4 a[4];
    #pragma unroll
    for (int k = 0; k < 4; k++) a[k] = e4[(size_t)w * 128 + k * 32 + lane];
    const float sqi = g_sq[w];
    const int c = labels[w];
    const int cnt = g_ccnt[c];
    float m2 = -CUDART_INF_F;
    for (int m = 0; m < cnt; m++) {
        const int j = g_cidx[c * BDIM + m];
        if (j == w) continue;
        float p = 0.f;
        #pragma unroll
        for (int k = 0; k < 4; k++) {
            float4 b = e4[(size_t)j * 128 + k * 32 + lane];
            p += a[k].x * b.x + a[k].y * b.y + a[k].z * b.z + a[k].w * b.w;
        }
        #pragma unroll
        for (int o = 16; o > 0; o >>= 1) p += __shfl_xor_sync(0xFFFFFFFF, p, o);
        const float d2 = sqi + g_sq[j] - 2.f * p;
        if (d2 > 0.f) m2 = fmaxf(m2, d2);
    }
    if (lane == 0) g_hp2[w] = m2;
}

// ---------------- tf32 mma helpers ----------------
__device__ __forceinline__ uint32_t f2tf32(float x) {
    uint32_t r;
    asm("cvt.rna.tf32.f32 %0, %1;" : "=r"(r) : "f"(x));
    return r;
}
__device__ __forceinline__ void mma8(float* c, const uint32_t* a, const uint32_t* b) {
    asm volatile(
        "mma.sync.aligned.m16n8k8.row.col.f32.tf32.tf32.f32 "
        "{%0,%1,%2,%3},{%4,%5,%6,%7},{%8,%9},{%0,%1,%2,%3};"
        : "+f"(c[0]), "+f"(c[1]), "+f"(c[2]), "+f"(c[3])
        : "r"(a[0]), "r"(a[1]), "r"(a[2]), "r"(a[3]), "r"(b[0]), "r"(b[1]));
}

#define SSTRIDE 36                       // floats per smem row (padded)
#define TILE_FLOATS (128 * SSTRIDE)      // one buffer = 4608 floats = 18 KB
#define DYN_SMEM_BYTES (4 * TILE_FLOATS * 4)   // As[2] + Bs[2] = 73728 bytes

// ---------------- mma GEMM (upper triangle) + fused negative-min epilogue ----------------
// 128x128 tile, 256 threads = 8 warps (2x4), warp tile 64x32, K chunks of 32.
__global__ void __launch_bounds__(256) gemm_mma(const float* __restrict__ emb,
                                                const int* __restrict__ labels) {
    extern __shared__ float dyn[];
    float* Abuf[2] = { dyn,                  dyn + TILE_FLOATS };
    float* Bbuf[2] = { dyn + 2 * TILE_FLOATS, dyn + 3 * TILE_FLOATS };

    __shared__ int s_rall[128], s_rsem[128], s_call[128], s_csem[128];
    __shared__ float s_sqi[128], s_sqj[128], s_hp2i[128], s_hp2j[128];
    __shared__ int s_li[128], s_lj[128];

    int rem = blockIdx.x, by = 0;
    while (rem >= TILES - by) { rem -= TILES - by; by++; }
    const int bx = by + rem;
    const bool diag = (bx == by);
    const int rowBase = by * 128;
    const int colBase = bx * 128;

    const int tid = threadIdx.x;
    const int wid = tid >> 5;
    const int lane = tid & 31;
    const int g = lane >> 2;     // 0..7
    const int t = lane & 3;      // 0..3
    const int mBase = (wid >> 2) * 64;
    const int nBase = (wid & 3) * 32;

    if (tid < 128) {
        s_rall[tid] = 0x7F800000; s_rsem[tid] = 0x7F800000;
        s_call[tid] = 0x7F800000; s_csem[tid] = 0x7F800000;
        const int gi = rowBase + tid, gj = colBase + tid;
        s_sqi[tid] = g_sq[gi]; s_hp2i[tid] = g_hp2[gi]; s_li[tid] = labels[gi];
        s_sqj[tid] = g_sq[gj]; s_hp2j[tid] = g_hp2[gj]; s_lj[tid] = labels[gj];
    }

    float acc[4][4][4];   // [mf][nf][reg]
    #pragma unroll
    for (int mf = 0; mf < 4; mf++)
        #pragma unroll
        for (int nf = 0; nf < 4; nf++)
            #pragma unroll
            for (int r = 0; r < 4; r++) acc[mf][nf][r] = 0.f;

    // preload chunk 0 (1024 float4 per tile / 256 threads = 4 each)
    {
        #pragma unroll
        for (int q = 0; q < 4; q++) {
            const int idx = tid + q * 256;
            const int row = idx >> 3, f4 = idx & 7;
            float4 av = *(const float4*)(emb + (size_t)(rowBase + row) * DDIM + f4 * 4);
            *(float4*)&Abuf[0][row * SSTRIDE + f4 * 4] = av;
            if (!diag) {
                float4 bv = *(const float4*)(emb + (size_t)(colBase + row) * DDIM + f4 * 4);
                *(float4*)&Bbuf[0][row * SSTRIDE + f4 * 4] = bv;
            }
        }
    }
    __syncthreads();

    for (int c = 0; c < 16; c++) {
        const int buf = c & 1;
        float4 stgA[4], stgB[4];
        if (c + 1 < 16) {
            const int k0 = (c + 1) * 32;
            #pragma unroll
            for (int q = 0; q < 4; q++) {
                const int idx = tid + q * 256;
                const int row = idx >> 3, f4 = idx & 7;
                stgA[q] = *(const float4*)(emb + (size_t)(rowBase + row) * DDIM + k0 + f4 * 4);
                if (!diag)
                    stgB[q] = *(const float4*)(emb + (size_t)(colBase + row) * DDIM + k0 + f4 * 4);
            }
        }

        const float* A = Abuf[buf];
        const float* B = diag ? Abuf[buf] : Bbuf[buf];

        #pragma unroll
        for (int s = 0; s < 4; s++) {
            const int k = s * 8 + t;
            uint32_t af[4][4], bf[4][2];
            #pragma unroll
            for (int mf = 0; mf < 4; mf++) {
                const int r0 = mBase + mf * 16 + g;
                af[mf][0] = f2tf32(A[r0 * SSTRIDE + k]);
                af[mf][1] = f2tf32(A[(r0 + 8) * SSTRIDE + k]);
                af[mf][2] = f2tf32(A[r0 * SSTRIDE + k + 4]);
                af[mf][3] = f2tf32(A[(r0 + 8) * SSTRIDE + k + 4]);
            }
            #pragma unroll
            for (int nf = 0; nf < 4; nf++) {
                const int n = nBase + nf * 8 + g;
                bf[nf][0] = f2tf32(B[n * SSTRIDE + k]);
                bf[nf][1] = f2tf32(B[n * SSTRIDE + k + 4]);
            }
            #pragma unroll
            for (int mf = 0; mf < 4; mf++)
                #pragma unroll
                for (int nf = 0; nf < 4; nf++)
                    mma8(acc[mf][nf], af[mf], bf[nf]);
        }
        __syncthreads();
        if (c + 1 < 16) {
            const int nbuf = buf ^ 1;
            #pragma unroll
            for (int q = 0; q < 4; q++) {
                const int idx = tid + q * 256;
                const int row = idx >> 3, f4 = idx & 7;
                *(float4*)&Abuf[nbuf][row * SSTRIDE + f4 * 4] = stgA[q];
                if (!diag) *(float4*)&Bbuf[nbuf][row * SSTRIDE + f4 * 4] = stgB[q];
            }
            __syncthreads();
        }
    }

    // ---------------- epilogue ----------------
    // thread owns rows: mBase + mf*16 + g + 8h, cols: nBase + nf*8 + 2t + b
    float rAll[4][2], rSem[4][2];
    float cAll[4][2], cSem[4][2];
    #pragma unroll
    for (int x = 0; x < 4; x++)
        #pragma unroll
        for (int y = 0; y < 2; y++) {
            rAll[x][y] = CUDART_INF_F; rSem[x][y] = CUDART_INF_F;
            cAll[x][y] = CUDART_INF_F; cSem[x][y] = CUDART_INF_F;
        }

    #pragma unroll
    for (int mf = 0; mf < 4; mf++) {
        #pragma unroll
        for (int h = 0; h < 2; h++) {
            const int rloc = mBase + mf * 16 + g + 8 * h;
            const float sqi = s_sqi[rloc];
            const int li = s_li[rloc];
            const float hp2i = s_hp2i[rloc];
            #pragma unroll
            for (int nf = 0; nf < 4; nf++) {
                #pragma unroll
                for (int b = 0; b < 2; b++) {
                    const int cloc = nBase + nf * 8 + 2 * t + b;
                    const float dot = acc[mf][nf][2 * h + b];
                    const float v = fmaxf(sqi + s_sqj[cloc] - 2.f * dot, 0.f);
                    const bool neg = (li != s_lj[cloc]);
                    const float va = neg ? v : CUDART_INF_F;
                    const float vsr = (neg && v > hp2i) ? v : CUDART_INF_F;
                    const float vsc = (neg && v > s_hp2j[cloc]) ? v : CUDART_INF_F;
                    rAll[mf][h] = fminf(rAll[mf][h], va);
                    rSem[mf][h] = fminf(rSem[mf][h], vsr);
                    cAll[nf][b] = fminf(cAll[nf][b], va);
                    cSem[nf][b] = fminf(cSem[nf][b], vsc);
                }
            }
        }
    }

    // row-side: min over 4 lanes (t) sharing each row
    #pragma unroll
    for (int mf = 0; mf < 4; mf++)
        #pragma unroll
        for (int h = 0; h < 2; h++) {
            float a = rAll[mf][h], s = rSem[mf][h];
            #pragma unroll
            for (int o = 1; o < 4; o <<= 1) {
                a = fminf(a, __shfl_xor_sync(0xFFFFFFFF, a, o));
                s = fminf(s, __shfl_xor_sync(0xFFFFFFFF, s, o));
            }
            if (t == 0) {
                const int rloc = mBase + mf * 16 + g + 8 * h;
                atomicMin(&s_rall[rloc], __float_as_int(a));
                atomicMin(&s_rsem[rloc], __float_as_int(s));
            }
        }
    // col-side: min over 8 lanes (g) sharing each col
    #pragma unroll
    for (int nf = 0; nf < 4; nf++)
        #pragma unroll
        for (int b = 0; b < 2; b++) {
            float a = cAll[nf][b], s = cSem[nf][b];
            #pragma unroll
            for (int o = 4; o < 32; o <<= 1) {
                a = fminf(a, __shfl_xor_sync(0xFFFFFFFF, a, o));
                s = fminf(s, __shfl_xor_sync(0xFFFFFFFF, s, o));
            }
            if (g == 0) {
                const int cloc = nBase + nf * 8 + 2 * t + b;
                atomicMin(&s_call[cloc], __float_as_int(a));
                atomicMin(&s_csem[cloc], __float_as_int(s));
            }
        }
    __syncthreads();

    if (tid < 128) {
        g_all2[(size_t)bx * BDIM + rowBase + tid] = __int_as_float(s_rall[tid]);
        g_semi2[(size_t)bx * BDIM + rowBase + tid] = __int_as_float(s_rsem[tid]);
        if (!diag) {
            g_all2[(size_t)by * BDIM + colBase + tid] = __int_as_float(s_call[tid]);
            g_semi2[(size_t)by * BDIM + colBase + tid] = __int_as_float(s_csem[tid]);
        }
    }
}

// ---------------- per-row finish ----------------
__global__ void __launch_bounds__(256) rowfinish() {
    const int r = blockIdx.x * 256 + threadIdx.x;
    float mA = CUDART_INF_F, mS = CUDART_INF_F;
    #pragma unroll 8
    for (int tt = 0; tt < TILES; tt++) {
        mA = fminf(mA, g_all2[(size_t)tt * BDIM + r]);
        mS = fminf(mS, g_semi2[(size_t)tt * BDIM + r]);
    }
    const float hn2 = (mS < CUDART_INF_F) ? mS : mA;
    const float hp2 = g_hp2[r];
    float loss = 0.f;
    if (hp2 >= 0.f) {
        const float l = sqrtf(hp2) - sqrtf(hn2) + MARGIN;
        loss = fmaxf(l, 0.f);
    }
    g_loss[r] = loss;
}

__global__ void __launch_bounds__(256) final_reduce(float* __restrict__ out) {
    const int tid = threadIdx.x;
    float acc = 0.f;
    for (int k = tid; k < BDIM; k += 256) acc += g_loss[k];
    __shared__ float s[256];
    s[tid] = acc;
    __syncthreads();
    #pragma unroll
    for (int st = 128; st > 0; st >>= 1) {
        if (tid < st) s[tid] += s[tid + st];
        __syncthreads();
    }
    if (tid == 0) out[0] = s[0] / (float)BDIM;
}

// ---------------- launch ----------------
extern "C" void kernel_launch(void* const* d_in, const int* in_sizes, int n_in,
                              void* d_out, int out_size) {
    const float* emb = (const float*)d_in[0];
    const int* labels = (const int*)d_in[1];
    float* out = (float*)d_out;

    cudaFuncSetAttribute(gemm_mma, cudaFuncAttributeMaxDynamicSharedMemorySize,
                         DYN_SMEM_BYTES);

    init_cnt<<<2, 256>>>();
    sqnorm_kernel<<<BDIM, 128>>>(emb);
    scatter_cls<<<BDIM / 256, 256>>>(labels);
    hp_kernel<<<BDIM / 8, 256>>>(emb, labels);
    gemm_mma<<<NTRI, 256, DYN_SMEM_BYTES>>>(emb, labels);
    rowfinish<<<BDIM / 256, 256>>>();
    final_reduce<<<1, 256>>>(out);
}

// round 7
// speedup vs baseline: 7.1096x; 1.6385x over previous
#include <cuda_runtime.h>
#include <cuda_fp16.h>
#include <math_constants.h>
#include <cstdint>

#define BDIM 8192
#define DDIM 512
#define MARGIN 0.2f
#define TILES 64
#define NTRI  (TILES * (TILES + 1) / 2)

// ---------------- scratch ----------------
__device__ float g_sq[BDIM];
__device__ float g_hp2[BDIM];
__device__ float g_all2[TILES * BDIM];
__device__ float g_semi2[TILES * BDIM];
__device__ float g_loss[BDIM];
__device__ int   g_ccnt[512];
__device__ int   g_cidx[512 * BDIM];

// ---------------- small kernels ----------------
__global__ void init_cnt() {
    int i = blockIdx.x * blockDim.x + threadIdx.x;
    if (i < 512) g_ccnt[i] = 0;
}

__global__ void __launch_bounds__(128) sqnorm_kernel(const float* __restrict__ emb) {
    const int i = blockIdx.x;
    const int tid = threadIdx.x;
    float4 v = ((const float4*)(emb + (size_t)i * DDIM))[tid];
    float s = v.x * v.x + v.y * v.y + v.z * v.z + v.w * v.w;
    #pragma unroll
    for (int o = 16; o > 0; o >>= 1) s += __shfl_down_sync(0xFFFFFFFF, s, o);
    __shared__ float ws[4];
    if ((tid & 31) == 0) ws[tid >> 5] = s;
    __syncthreads();
    if (tid == 0) g_sq[i] = ws[0] + ws[1] + ws[2] + ws[3];
}

__global__ void scatter_cls(const int* __restrict__ labels) {
    int i = blockIdx.x * blockDim.x + threadIdx.x;
    if (i < BDIM) {
        int c = labels[i];
        int s = atomicAdd(&g_ccnt[c], 1);
        g_cidx[c * BDIM + s] = i;
    }
}

// 2-way ILP over class members to hide shfl-reduction latency.
__global__ void __launch_bounds__(256) hp_kernel(const float* __restrict__ emb,
                                                 const int* __restrict__ labels) {
    const int w = blockIdx.x * 8 + (threadIdx.x >> 5);
    const int lane = threadIdx.x & 31;
    const float4* e4 = (const float4*)emb;
    float4 a[4];
    #pragma unroll
    for (int k = 0; k < 4; k++) a[k] = e4[(size_t)w * 128 + k * 32 + lane];
    const float sqi = g_sq[w];
    const int c = labels[w];
    const int cnt = g_ccnt[c];
    float m2 = -CUDART_INF_F;
    for (int m = 0; m < cnt; m += 2) {
        const int j0 = g_cidx[c * BDIM + m];
        const int j1 = (m + 1 < cnt) ? g_cidx[c * BDIM + m + 1] : j0;
        float p0 = 0.f, p1 = 0.f;
        #pragma unroll
        for (int k = 0; k < 4; k++) {
            float4 b0 = e4[(size_t)j0 * 128 + k * 32 + lane];
            float4 b1 = e4[(size_t)j1 * 128 + k * 32 + lane];
            p0 += a[k].x * b0.x + a[k].y * b0.y + a[k].z * b0.z + a[k].w * b0.w;
            p1 += a[k].x * b1.x + a[k].y * b1.y + a[k].z * b1.z + a[k].w * b1.w;
        }
        #pragma unroll
        for (int o = 16; o > 0; o >>= 1) {
            p0 += __shfl_xor_sync(0xFFFFFFFF, p0, o);
            p1 += __shfl_xor_sync(0xFFFFFFFF, p1, o);
        }
        if (j0 != w) {
            const float d2 = sqi + g_sq[j0] - 2.f * p0;
            if (d2 > 0.f) m2 = fmaxf(m2, d2);
        }
        if (j1 != w && m + 1 < cnt) {
            const float d2 = sqi + g_sq[j1] - 2.f * p1;
            if (d2 > 0.f) m2 = fmaxf(m2, d2);
        }
    }
    if (lane == 0) g_hp2[w] = m2;
}

// ---------------- fp16 mma helper ----------------
__device__ __forceinline__ void mma16(float* c, const uint32_t* a, const uint32_t* b) {
    asm volatile(
        "mma.sync.aligned.m16n8k16.row.col.f32.f16.f16.f32 "
        "{%0,%1,%2,%3},{%4,%5,%6,%7},{%8,%9},{%0,%1,%2,%3};"
        : "+f"(c[0]), "+f"(c[1]), "+f"(c[2]), "+f"(c[3])
        : "r"(a[0]), "r"(a[1]), "r"(a[2]), "r"(a[3]), "r"(b[0]), "r"(b[1]));
}

__device__ __forceinline__ uint32_t pack_h2(float x, float y) {
    half2 h = __floats2half2_rn(x, y);
    return *reinterpret_cast<uint32_t*>(&h);
}

#define HSTRIDE 40   // halfs per smem row (80 B): conflict-free fragment reads

// ---------------- fp16 mma GEMM (upper triangle) + fused epilogue ----------------
// 128x128 tile, 256 threads = 8 warps (2x4), warp tile 64x32, K chunks of 32 (2 k16 steps).
__global__ void __launch_bounds__(256, 2) gemm_mma(const float* __restrict__ emb,
                                                   const int* __restrict__ labels) {
    __shared__ __align__(16) half Abuf[2][128 * HSTRIDE];
    __shared__ __align__(16) half Bbuf[2][128 * HSTRIDE];
    __shared__ int s_rall[128], s_rsem[128], s_call[128], s_csem[128];
    __shared__ float s_sqi[128], s_sqj[128], s_hp2i[128], s_hp2j[128];
    __shared__ int s_li[128], s_lj[128];

    int rem = blockIdx.x, by = 0;
    while (rem >= TILES - by) { rem -= TILES - by; by++; }
    const int bx = by + rem;
    const bool diag = (bx == by);
    const int rowBase = by * 128;
    const int colBase = bx * 128;

    const int tid = threadIdx.x;
    const int wid = tid >> 5;
    const int lane = tid & 31;
    const int g = lane >> 2;     // 0..7
    const int t = lane & 3;      // 0..3
    const int mBase = (wid >> 2) * 64;
    const int nBase = (wid & 3) * 32;

    if (tid < 128) {
        s_rall[tid] = 0x7F800000; s_rsem[tid] = 0x7F800000;
        s_call[tid] = 0x7F800000; s_csem[tid] = 0x7F800000;
        const int gi = rowBase + tid, gj = colBase + tid;
        s_sqi[tid] = g_sq[gi]; s_hp2i[tid] = g_hp2[gi]; s_li[tid] = labels[gi];
        s_sqj[tid] = g_sq[gj]; s_hp2j[tid] = g_hp2[gj]; s_lj[tid] = labels[gj];
    }

    float acc[4][4][4];
    #pragma unroll
    for (int mf = 0; mf < 4; mf++)
        #pragma unroll
        for (int nf = 0; nf < 4; nf++)
            #pragma unroll
            for (int r = 0; r < 4; r++) acc[mf][nf][r] = 0.f;

    // writer mapping: 1024 float4 per tile-chunk / 256 threads = 4 each
    const int wrow = tid >> 1;   // unused helper removed
    (void)wrow;

    // preload chunk 0
    {
        #pragma unroll
        for (int q = 0; q < 4; q++) {
            const int idx = tid + q * 256;
            const int row = idx >> 3, f4 = idx & 7;
            float4 av = *(const float4*)(emb + (size_t)(rowBase + row) * DDIM + f4 * 4);
            uint2 ua = make_uint2(pack_h2(av.x, av.y), pack_h2(av.z, av.w));
            *(uint2*)&Abuf[0][row * HSTRIDE + f4 * 4] = ua;
            if (!diag) {
                float4 bv = *(const float4*)(emb + (size_t)(colBase + row) * DDIM + f4 * 4);
                uint2 ub = make_uint2(pack_h2(bv.x, bv.y), pack_h2(bv.z, bv.w));
                *(uint2*)&Bbuf[0][row * HSTRIDE + f4 * 4] = ub;
            }
        }
    }
    __syncthreads();

    for (int c = 0; c < 16; c++) {
        const int buf = c & 1;
        float4 stgA[4], stgB[4];
        if (c + 1 < 16) {
            const int k0 = (c + 1) * 32;
            #pragma unroll
            for (int q = 0; q < 4; q++) {
                const int idx = tid + q * 256;
                const int row = idx >> 3, f4 = idx & 7;
                stgA[q] = *(const float4*)(emb + (size_t)(rowBase + row) * DDIM + k0 + f4 * 4);
                if (!diag)
                    stgB[q] = *(const float4*)(emb + (size_t)(colBase + row) * DDIM + k0 + f4 * 4);
            }
        }

        const half* A = Abuf[buf];
        const half* B = diag ? Abuf[buf] : Bbuf[buf];

        #pragma unroll
        for (int s = 0; s < 2; s++) {
            const int kb = s * 16 + 2 * t;
            uint32_t bf[4][2];
            #pragma unroll
            for (int nf = 0; nf < 4; nf++) {
                const int n = nBase + nf * 8 + g;
                bf[nf][0] = *(const uint32_t*)&B[n * HSTRIDE + kb];
                bf[nf][1] = *(const uint32_t*)&B[n * HSTRIDE + kb + 8];
            }
            #pragma unroll
            for (int mf = 0; mf < 4; mf++) {
                const int r0 = mBase + mf * 16 + g;
                uint32_t af[4];
                af[0] = *(const uint32_t*)&A[r0 * HSTRIDE + kb];
                af[1] = *(const uint32_t*)&A[(r0 + 8) * HSTRIDE + kb];
                af[2] = *(const uint32_t*)&A[r0 * HSTRIDE + kb + 8];
                af[3] = *(const uint32_t*)&A[(r0 + 8) * HSTRIDE + kb + 8];
                #pragma unroll
                for (int nf = 0; nf < 4; nf++)
                    mma16(acc[mf][nf], af, bf[nf]);
            }
        }
        __syncthreads();
        if (c + 1 < 16) {
            const int nbuf = buf ^ 1;
            #pragma unroll
            for (int q = 0; q < 4; q++) {
                const int idx = tid + q * 256;
                const int row = idx >> 3, f4 = idx & 7;
                uint2 ua = make_uint2(pack_h2(stgA[q].x, stgA[q].y), pack_h2(stgA[q].z, stgA[q].w));
                *(uint2*)&Abuf[nbuf][row * HSTRIDE + f4 * 4] = ua;
                if (!diag) {
                    uint2 ub = make_uint2(pack_h2(stgB[q].x, stgB[q].y), pack_h2(stgB[q].z, stgB[q].w));
                    *(uint2*)&Bbuf[nbuf][row * HSTRIDE + f4 * 4] = ub;
                }
            }
            __syncthreads();
        }
    }

    // ---------------- epilogue ----------------
    // thread owns rows: mBase + mf*16 + g + 8h, cols: nBase + nf*8 + 2t + b
    float rAll[4][2], rSem[4][2];
    float cAll[4][2], cSem[4][2];
    #pragma unroll
    for (int x = 0; x < 4; x++)
        #pragma unroll
        for (int y = 0; y < 2; y++) {
            rAll[x][y] = CUDART_INF_F; rSem[x][y] = CUDART_INF_F;
            cAll[x][y] = CUDART_INF_F; cSem[x][y] = CUDART_INF_F;
        }

    #pragma unroll
    for (int mf = 0; mf < 4; mf++) {
        #pragma unroll
        for (int h = 0; h < 2; h++) {
            const int rloc = mBase + mf * 16 + g + 8 * h;
            const float sqi = s_sqi[rloc];
            const int li = s_li[rloc];
            const float hp2i = s_hp2i[rloc];
            #pragma unroll
            for (int nf = 0; nf < 4; nf++) {
                #pragma unroll
                for (int b = 0; b < 2; b++) {
                    const int cloc = nBase + nf * 8 + 2 * t + b;
                    const float dot = acc[mf][nf][2 * h + b];
                    const float v = fmaxf(sqi + s_sqj[cloc] - 2.f * dot, 0.f);
                    const bool neg = (li != s_lj[cloc]);
                    const float va = neg ? v : CUDART_INF_F;
                    const float vsr = (neg && v > hp2i) ? v : CUDART_INF_F;
                    const float vsc = (neg && v > s_hp2j[cloc]) ? v : CUDART_INF_F;
                    rAll[mf][h] = fminf(rAll[mf][h], va);
                    rSem[mf][h] = fminf(rSem[mf][h], vsr);
                    cAll[nf][b] = fminf(cAll[nf][b], va);
                    cSem[nf][b] = fminf(cSem[nf][b], vsc);
                }
            }
        }
    }

    #pragma unroll
    for (int mf = 0; mf < 4; mf++)
        #pragma unroll
        for (int h = 0; h < 2; h++) {
            float a = rAll[mf][h], s = rSem[mf][h];
            #pragma unroll
            for (int o = 1; o < 4; o <<= 1) {
                a = fminf(a, __shfl_xor_sync(0xFFFFFFFF, a, o));
                s = fminf(s, __shfl_xor_sync(0xFFFFFFFF, s, o));
            }
            if (t == 0) {
                const int rloc = mBase + mf * 16 + g + 8 * h;
                atomicMin(&s_rall[rloc], __float_as_int(a));
                atomicMin(&s_rsem[rloc], __float_as_int(s));
            }
        }
    #pragma unroll
    for (int nf = 0; nf < 4; nf++)
        #pragma unroll
        for (int b = 0; b < 2; b++) {
            float a = cAll[nf][b], s = cSem[nf][b];
            #pragma unroll
            for (int o = 4; o < 32; o <<= 1) {
                a = fminf(a, __shfl_xor_sync(0xFFFFFFFF, a, o));
                s = fminf(s, __shfl_xor_sync(0xFFFFFFFF, s, o));
            }
            if (g == 0) {
                const int cloc = nBase + nf * 8 + 2 * t + b;
                atomicMin(&s_call[cloc], __float_as_int(a));
                atomicMin(&s_csem[cloc], __float_as_int(s));
            }
        }
    __syncthreads();

    if (tid < 128) {
        g_all2[(size_t)bx * BDIM + rowBase + tid] = __int_as_float(s_rall[tid]);
        g_semi2[(size_t)bx * BDIM + rowBase + tid] = __int_as_float(s_rsem[tid]);
        if (!diag) {
            g_all2[(size_t)by * BDIM + colBase + tid] = __int_as_float(s_call[tid]);
            g_semi2[(size_t)by * BDIM + colBase + tid] = __int_as_float(s_csem[tid]);
        }
    }
}

// ---------------- per-row finish ----------------
__global__ void __launch_bounds__(256) rowfinish() {
    const int r = blockIdx.x * 256 + threadIdx.x;
    float mA = CUDART_INF_F, mS = CUDART_INF_F;
    #pragma unroll 8
    for (int tt = 0; tt < TILES; tt++) {
        mA = fminf(mA, g_all2[(size_t)tt * BDIM + r]);
        mS = fminf(mS, g_semi2[(size_t)tt * BDIM + r]);
    }
    const float hn2 = (mS < CUDART_INF_F) ? mS : mA;
    const float hp2 = g_hp2[r];
    float loss = 0.f;
    if (hp2 >= 0.f) {
        const float l = sqrtf(hp2) - sqrtf(hn2) + MARGIN;
        loss = fmaxf(l, 0.f);
    }
    g_loss[r] = loss;
}

__global__ void __launch_bounds__(256) final_reduce(float* __restrict__ out) {
    const int tid = threadIdx.x;
    float acc = 0.f;
    for (int k = tid; k < BDIM; k += 256) acc += g_loss[k];
    __shared__ float s[256];
    s[tid] = acc;
    __syncthreads();
    #pragma unroll
    for (int st = 128; st > 0; st >>= 1) {
        if (tid < st) s[tid] += s[tid + st];
        __syncthreads();
    }
    if (tid == 0) out[0] = s[0] / (float)BDIM;
}

// ---------------- launch ----------------
extern "C" void kernel_launch(void* const* d_in, const int* in_sizes, int n_in,
                              void* d_out, int out_size) {
    const float* emb = (const float*)d_in[0];
    const int* labels = (const int*)d_in[1];
    float* out = (float*)d_out;

    init_cnt<<<2, 256>>>();
    sqnorm_kernel<<<BDIM, 128>>>(emb);
    scatter_cls<<<BDIM / 256, 256>>>(labels);
    hp_kernel<<<BDIM / 8, 256>>>(emb, labels);
    gemm_mma<<<NTRI, 256>>>(emb, labels);
    rowfinish<<<BDIM / 256, 256>>>();
    final_reduce<<<1, 256>>>(out);
}

// round 8
// speedup vs baseline: 7.9378x; 1.1165x over previous
#include <cuda_runtime.h>
#include <cuda_fp16.h>
#include <math_constants.h>
#include <cstdint>

#define BDIM 8192
#define DDIM 512
#define MARGIN 0.2f
#define TILES 64
#define NTRI  (TILES * (TILES + 1) / 2)
#define HPMAXM 88
#define HPBYTES (HPMAXM * DDIM * 2)

// ---------------- scratch ----------------
__device__ float g_sq[BDIM];
__device__ float g_hp2[BDIM];
__device__ float g_all2[TILES * BDIM];
__device__ float g_semi2[TILES * BDIM];
__device__ float g_loss[BDIM];
__device__ int   g_ccnt[512];
__device__ int   g_cidx[512 * BDIM];

__device__ __forceinline__ uint32_t pack_h2(float x, float y) {
    half2 h = __floats2half2_rn(x, y);
    return *reinterpret_cast<uint32_t*>(&h);
}

// ---------------- sqnorm (+ init cnt & hp2) ----------------
__global__ void __launch_bounds__(128) sqnorm_kernel(const float* __restrict__ emb) {
    const int i = blockIdx.x;
    const int tid = threadIdx.x;
    if (i < 4) g_ccnt[i * 128 + tid] = 0;
    if (tid == 0) g_hp2[i] = -CUDART_INF_F;
    float4 v = ((const float4*)(emb + (size_t)i * DDIM))[tid];
    float s = v.x * v.x + v.y * v.y + v.z * v.z + v.w * v.w;
    #pragma unroll
    for (int o = 16; o > 0; o >>= 1) s += __shfl_down_sync(0xFFFFFFFF, s, o);
    __shared__ float ws[4];
    if ((tid & 31) == 0) ws[tid >> 5] = s;
    __syncthreads();
    if (tid == 0) g_sq[i] = ws[0] + ws[1] + ws[2] + ws[3];
}

__global__ void scatter_cls(const int* __restrict__ labels) {
    int i = blockIdx.x * blockDim.x + threadIdx.x;
    if (i < BDIM) {
        int c = labels[i];
        int s = atomicAdd(&g_ccnt[c], 1);
        g_cidx[c * BDIM + s] = i;
    }
}

// ---------------- hardest positive: one block per class ----------------
// Stage all class members as fp16 in smem; 8 warps sweep intra-class pairs.
// smem layout: interleaved so lane reads word (row*256 + q*32 + lane): conflict-free.
__global__ void __launch_bounds__(256) hp_kernel(const float* __restrict__ emb) {
    extern __shared__ uint32_t sh[];   // [m][256] half2 words
    __shared__ int s_idx[HPMAXM];
    __shared__ float s_sq[HPMAXM];

    const int c = blockIdx.x;
    const int cnt = min(g_ccnt[c], HPMAXM);
    const int tid = threadIdx.x;

    for (int m = tid; m < cnt; m += 256) {
        const int gi = g_cidx[c * BDIM + m];
        s_idx[m] = gi;
        s_sq[m] = g_sq[gi];
    }
    __syncthreads();
    // load member rows -> fp16 smem (word layout: m*256 + (col/2))
    for (int idx = tid; idx < cnt * 128; idx += 256) {
        const int m = idx >> 7, f = idx & 127;
        float4 v = ((const float4*)(emb + (size_t)s_idx[m] * DDIM))[f];
        sh[m * 256 + f * 2]     = pack_h2(v.x, v.y);
        sh[m * 256 + f * 2 + 1] = pack_h2(v.z, v.w);
    }
    __syncthreads();

    const int wid = tid >> 5, lane = tid & 31;
    for (int i = wid; i < cnt - 1; i += 8) {
        // lane covers word cols lane, lane+32, ..., lane+224
        float2 a[8];
        #pragma unroll
        for (int q = 0; q < 8; q++) {
            half2 h = *(half2*)&sh[i * 256 + q * 32 + lane];
            a[q] = __half22float2(h);
        }
        const float sqi = s_sq[i];
        const int gi = s_idx[i];
        for (int j = i + 1; j < cnt; j++) {
            float p = 0.f;
            #pragma unroll
            for (int q = 0; q < 8; q++) {
                half2 h = *(half2*)&sh[j * 256 + q * 32 + lane];
                float2 b = __half22float2(h);
                p += a[q].x * b.x + a[q].y * b.y;
            }
            #pragma unroll
            for (int o = 16; o > 0; o >>= 1) p += __shfl_xor_sync(0xFFFFFFFF, p, o);
            if (lane == 0) {
                const float d2 = sqi + s_sq[j] - 2.f * p;
                if (d2 > 0.f) {
                    atomicMax((int*)&g_hp2[gi], __float_as_int(d2));
                    atomicMax((int*)&g_hp2[s_idx[j]], __float_as_int(d2));
                }
            }
        }
    }
}

// ---------------- fp16 mma helper ----------------
__device__ __forceinline__ void mma16(float* c, const uint32_t* a, const uint32_t* b) {
    asm volatile(
        "mma.sync.aligned.m16n8k16.row.col.f32.f16.f16.f32 "
        "{%0,%1,%2,%3},{%4,%5,%6,%7},{%8,%9},{%0,%1,%2,%3};"
        : "+f"(c[0]), "+f"(c[1]), "+f"(c[2]), "+f"(c[3])
        : "r"(a[0]), "r"(a[1]), "r"(a[2]), "r"(a[3]), "r"(b[0]), "r"(b[1]));
}
__device__ __forceinline__ void ldsm4(uint32_t& r0, uint32_t& r1, uint32_t& r2, uint32_t& r3,
                                      uint32_t addr) {
    asm volatile("ldmatrix.sync.aligned.m8n8.x4.shared.b16 {%0,%1,%2,%3}, [%4];"
                 : "=r"(r0), "=r"(r1), "=r"(r2), "=r"(r3) : "r"(addr));
}

#define HSTRIDE 40   // halfs per smem row (80 B): conflict-free ldmatrix phases

// ---------------- fp16 mma GEMM (upper triangle) + fused epilogue ----------------
__global__ void __launch_bounds__(256, 2) gemm_mma(const float* __restrict__ emb,
                                                   const int* __restrict__ labels) {
    __shared__ __align__(16) half Abuf[2][128 * HSTRIDE];
    __shared__ __align__(16) half Bbuf[2][128 * HSTRIDE];
    __shared__ int s_rall[128], s_rsem[128], s_call[128], s_csem[128];
    __shared__ float s_sqi[128], s_sqj[128], s_hp2i[128], s_hp2j[128];
    __shared__ int s_li[128], s_lj[128];

    int rem = blockIdx.x, by = 0;
    while (rem >= TILES - by) { rem -= TILES - by; by++; }
    const int bx = by + rem;
    const bool diag = (bx == by);
    const int rowBase = by * 128;
    const int colBase = bx * 128;

    const int tid = threadIdx.x;
    const int wid = tid >> 5;
    const int lane = tid & 31;
    const int g = lane >> 2;
    const int t = lane & 3;
    const int mBase = (wid >> 2) * 64;
    const int nBase = (wid & 3) * 32;

    if (tid < 128) {
        s_rall[tid] = 0x7F800000; s_rsem[tid] = 0x7F800000;
        s_call[tid] = 0x7F800000; s_csem[tid] = 0x7F800000;
        const int gi = rowBase + tid, gj = colBase + tid;
        s_sqi[tid] = g_sq[gi]; s_hp2i[tid] = g_hp2[gi]; s_li[tid] = labels[gi];
        s_sqj[tid] = g_sq[gj]; s_hp2j[tid] = g_hp2[gj]; s_lj[tid] = labels[gj];
    }

    float acc[4][4][4];
    #pragma unroll
    for (int mf = 0; mf < 4; mf++)
        #pragma unroll
        for (int nf = 0; nf < 4; nf++)
            #pragma unroll
            for (int r = 0; r < 4; r++) acc[mf][nf][r] = 0.f;

    // ldmatrix per-lane address components
    const int arow = (lane & 7) + (((lane >> 3) & 1) << 3);
    const int acol = (lane >> 4) << 3;
    const int brow = ((lane >> 4) << 3) + (lane & 7);
    const int bcol = ((lane >> 3) & 1) << 3;

    // preload chunk 0
    {
        #pragma unroll
        for (int q = 0; q < 4; q++) {
            const int idx = tid + q * 256;
            const int row = idx >> 3, f4 = idx & 7;
            float4 av = *(const float4*)(emb + (size_t)(rowBase + row) * DDIM + f4 * 4);
            *(uint2*)&Abuf[0][row * HSTRIDE + f4 * 4] =
                make_uint2(pack_h2(av.x, av.y), pack_h2(av.z, av.w));
            if (!diag) {
                float4 bv = *(const float4*)(emb + (size_t)(colBase + row) * DDIM + f4 * 4);
                *(uint2*)&Bbuf[0][row * HSTRIDE + f4 * 4] =
                    make_uint2(pack_h2(bv.x, bv.y), pack_h2(bv.z, bv.w));
            }
        }
    }
    __syncthreads();

    for (int c = 0; c < 16; c++) {
        const int buf = c & 1;
        float4 stgA[4], stgB[4];
        if (c + 1 < 16) {
            const int k0 = (c + 1) * 32;
            #pragma unroll
            for (int q = 0; q < 4; q++) {
                const int idx = tid + q * 256;
                const int row = idx >> 3, f4 = idx & 7;
                stgA[q] = *(const float4*)(emb + (size_t)(rowBase + row) * DDIM + k0 + f4 * 4);
                if (!diag)
                    stgB[q] = *(const float4*)(emb + (size_t)(colBase + row) * DDIM + k0 + f4 * 4);
            }
        }

        const uint32_t Ash = (uint32_t)__cvta_generic_to_shared(&Abuf[buf][0]);
        const uint32_t Bsh = diag ? Ash : (uint32_t)__cvta_generic_to_shared(&Bbuf[buf][0]);

        #pragma unroll
        for (int s = 0; s < 2; s++) {
            const int kb0 = s * 16;
            uint32_t bf[4][2];
            #pragma unroll
            for (int q = 0; q < 2; q++) {
                const uint32_t baddr = Bsh +
                    (((nBase + q * 16 + brow) * HSTRIDE + kb0 + bcol) << 1);
                ldsm4(bf[2 * q][0], bf[2 * q][1], bf[2 * q + 1][0], bf[2 * q + 1][1], baddr);
            }
            #pragma unroll
            for (int mf = 0; mf < 4; mf++) {
                uint32_t af[4];
                const uint32_t aaddr = Ash +
                    (((mBase + mf * 16 + arow) * HSTRIDE + kb0 + acol) << 1);
                ldsm4(af[0], af[1], af[2], af[3], aaddr);
                #pragma unroll
                for (int nf = 0; nf < 4; nf++)
                    mma16(acc[mf][nf], af, bf[nf]);
            }
        }
        __syncthreads();
        if (c + 1 < 16) {
            const int nbuf = buf ^ 1;
            #pragma unroll
            for (int q = 0; q < 4; q++) {
                const int idx = tid + q * 256;
                const int row = idx >> 3, f4 = idx & 7;
                *(uint2*)&Abuf[nbuf][row * HSTRIDE + f4 * 4] =
                    make_uint2(pack_h2(stgA[q].x, stgA[q].y), pack_h2(stgA[q].z, stgA[q].w));
                if (!diag)
                    *(uint2*)&Bbuf[nbuf][row * HSTRIDE + f4 * 4] =
                        make_uint2(pack_h2(stgB[q].x, stgB[q].y), pack_h2(stgB[q].z, stgB[q].w));
            }
            __syncthreads();
        }
    }

    // ---------------- epilogue ----------------
    float rAll[4][2], rSem[4][2], cAll[4][2], cSem[4][2];
    #pragma unroll
    for (int x = 0; x < 4; x++)
        #pragma unroll
        for (int y = 0; y < 2; y++) {
            rAll[x][y] = CUDART_INF_F; rSem[x][y] = CUDART_INF_F;
            cAll[x][y] = CUDART_INF_F; cSem[x][y] = CUDART_INF_F;
        }

    #pragma unroll
    for (int mf = 0; mf < 4; mf++) {
        #pragma unroll
        for (int h = 0; h < 2; h++) {
            const int rloc = mBase + mf * 16 + g + 8 * h;
            const float sqi = s_sqi[rloc];
            const int li = s_li[rloc];
            const float hp2i = s_hp2i[rloc];
            #pragma unroll
            for (int nf = 0; nf < 4; nf++) {
                #pragma unroll
                for (int b = 0; b < 2; b++) {
                    const int cloc = nBase + nf * 8 + 2 * t + b;
                    const float dot = acc[mf][nf][2 * h + b];
                    const float v = fmaxf(sqi + s_sqj[cloc] - 2.f * dot, 0.f);
                    const bool neg = (li != s_lj[cloc]);
                    const float va = neg ? v : CUDART_INF_F;
                    const float vsr = (neg && v > hp2i) ? v : CUDART_INF_F;
                    const float vsc = (neg && v > s_hp2j[cloc]) ? v : CUDART_INF_F;
                    rAll[mf][h] = fminf(rAll[mf][h], va);
                    rSem[mf][h] = fminf(rSem[mf][h], vsr);
                    cAll[nf][b] = fminf(cAll[nf][b], va);
                    cSem[nf][b] = fminf(cSem[nf][b], vsc);
                }
            }
        }
    }

    #pragma unroll
    for (int mf = 0; mf < 4; mf++)
        #pragma unroll
        for (int h = 0; h < 2; h++) {
            float a = rAll[mf][h], s = rSem[mf][h];
            #pragma unroll
            for (int o = 1; o < 4; o <<= 1) {
                a = fminf(a, __shfl_xor_sync(0xFFFFFFFF, a, o));
                s = fminf(s, __shfl_xor_sync(0xFFFFFFFF, s, o));
            }
            if (t == 0) {
                const int rloc = mBase + mf * 16 + g + 8 * h;
                atomicMin(&s_rall[rloc], __float_as_int(a));
                atomicMin(&s_rsem[rloc], __float_as_int(s));
            }
        }
    #pragma unroll
    for (int nf = 0; nf < 4; nf++)
        #pragma unroll
        for (int b = 0; b < 2; b++) {
            float a = cAll[nf][b], s = cSem[nf][b];
            #pragma unroll
            for (int o = 4; o < 32; o <<= 1) {
                a = fminf(a, __shfl_xor_sync(0xFFFFFFFF, a, o));
                s = fminf(s, __shfl_xor_sync(0xFFFFFFFF, s, o));
            }
            if (g == 0) {
                const int cloc = nBase + nf * 8 + 2 * t + b;
                atomicMin(&s_call[cloc], __float_as_int(a));
                atomicMin(&s_csem[cloc], __float_as_int(s));
            }
        }
    __syncthreads();

    if (tid < 128) {
        g_all2[(size_t)bx * BDIM + rowBase + tid] = __int_as_float(s_rall[tid]);
        g_semi2[(size_t)bx * BDIM + rowBase + tid] = __int_as_float(s_rsem[tid]);
        if (!diag) {
            g_all2[(size_t)by * BDIM + colBase + tid] = __int_as_float(s_call[tid]);
            g_semi2[(size_t)by * BDIM + colBase + tid] = __int_as_float(s_csem[tid]);
        }
    }
}

// ---------------- per-row finish ----------------
__global__ void __launch_bounds__(256) rowfinish() {
    const int r = blockIdx.x * 256 + threadIdx.x;
    float mA = CUDART_INF_F, mS = CUDART_INF_F;
    #pragma unroll 8
    for (int tt = 0; tt < TILES; tt++) {
        mA = fminf(mA, g_all2[(size_t)tt * BDIM + r]);
        mS = fminf(mS, g_semi2[(size_t)tt * BDIM + r]);
    }
    const float hn2 = (mS < CUDART_INF_F) ? mS : mA;
    const float hp2 = g_hp2[r];
    float loss = 0.f;
    if (hp2 >= 0.f) {
        const float l = sqrtf(hp2) - sqrtf(hn2) + MARGIN;
        loss = fmaxf(l, 0.f);
    }
    g_loss[r] = loss;
}

__global__ void __launch_bounds__(256) final_reduce(float* __restrict__ out) {
    const int tid = threadIdx.x;
    float acc = 0.f;
    for (int k = tid; k < BDIM; k += 256) acc += g_loss[k];
    __shared__ float s[256];
    s[tid] = acc;
    __syncthreads();
    #pragma unroll
    for (int st = 128; st > 0; st >>= 1) {
        if (tid < st) s[tid] += s[tid + st];
        __syncthreads();
    }
    if (tid == 0) out[0] = s[0] / (float)BDIM;
}

// ---------------- launch ----------------
extern "C" void kernel_launch(void* const* d_in, const int* in_sizes, int n_in,
                              void* d_out, int out_size) {
    const float* emb = (const float*)d_in[0];
    const int* labels = (const int*)d_in[1];
    float* out = (float*)d_out;

    cudaFuncSetAttribute(hp_kernel, cudaFuncAttributeMaxDynamicSharedMemorySize, HPBYTES);

    sqnorm_kernel<<<BDIM, 128>>>(emb);
    scatter_cls<<<BDIM / 256, 256>>>(labels);
    hp_kernel<<<512, 256, HPBYTES>>>(emb);
    gemm_mma<<<NTRI, 256>>>(emb, labels);
    rowfinish<<<BDIM / 256, 256>>>();
    final_reduce<<<1, 256>>>(out);
}

// round 9
// speedup vs baseline: 8.6371x; 1.0881x over previous
#include <cuda_runtime.h>
#include <cuda_fp16.h>
#include <math_constants.h>
#include <cstdint>

#define BDIM 8192
#define DDIM 512
#define MARGIN 0.2f
#define TILES 64
#define NTRI  (TILES * (TILES + 1) / 2)
#define HPMAXM 88
#define HPBYTES (HPMAXM * DDIM * 2)

// ---------------- scratch ----------------
__device__ __align__(16) half g_embh[(size_t)BDIM * DDIM];   // fp16 copy of embeddings (8 MB)
__device__ float g_sq[BDIM];
__device__ float g_hp2[BDIM];
__device__ float g_all2[TILES * BDIM];
__device__ float g_semi2[TILES * BDIM];
__device__ float g_loss[BDIM];
__device__ int   g_ccnt[512];
__device__ int   g_cidx[512 * BDIM];

__device__ __forceinline__ uint32_t pack_h2(float x, float y) {
    half2 h = __floats2half2_rn(x, y);
    return *reinterpret_cast<uint32_t*>(&h);
}

// ---------------- prep: fp16 convert + sqnorm + init ----------------
__global__ void __launch_bounds__(128) prep_kernel(const float* __restrict__ emb) {
    const int i = blockIdx.x;
    const int tid = threadIdx.x;
    if (i < 4) g_ccnt[i * 128 + tid] = 0;
    if (tid == 0) g_hp2[i] = -CUDART_INF_F;
    float4 v = ((const float4*)(emb + (size_t)i * DDIM))[tid];
    ((uint2*)(g_embh + (size_t)i * DDIM))[tid] =
        make_uint2(pack_h2(v.x, v.y), pack_h2(v.z, v.w));
    float s = v.x * v.x + v.y * v.y + v.z * v.z + v.w * v.w;
    #pragma unroll
    for (int o = 16; o > 0; o >>= 1) s += __shfl_down_sync(0xFFFFFFFF, s, o);
    __shared__ float ws[4];
    if ((tid & 31) == 0) ws[tid >> 5] = s;
    __syncthreads();
    if (tid == 0) g_sq[i] = ws[0] + ws[1] + ws[2] + ws[3];
}

__global__ void scatter_cls(const int* __restrict__ labels) {
    int i = blockIdx.x * blockDim.x + threadIdx.x;
    if (i < BDIM) {
        int c = labels[i];
        int s = atomicAdd(&g_ccnt[c], 1);
        g_cidx[c * BDIM + s] = i;
    }
}

// ---------------- hardest positive: one block per class (fp16 staged) ----------------
__global__ void __launch_bounds__(256) hp_kernel() {
    extern __shared__ uint32_t sh[];   // [m][256] half2 words
    __shared__ int s_idx[HPMAXM];
    __shared__ float s_sq[HPMAXM];

    const int c = blockIdx.x;
    const int cnt = min(g_ccnt[c], HPMAXM);
    const int tid = threadIdx.x;

    for (int m = tid; m < cnt; m += 256) {
        const int gi = g_cidx[c * BDIM + m];
        s_idx[m] = gi;
        s_sq[m] = g_sq[gi];
    }
    __syncthreads();
    for (int idx = tid; idx < cnt * 64; idx += 256) {
        const int m = idx >> 6, f = idx & 63;
        uint4 v = ((const uint4*)(g_embh + (size_t)s_idx[m] * DDIM))[f];
        *(uint4*)&sh[m * 256 + f * 4] = v;
    }
    __syncthreads();

    const int wid = tid >> 5, lane = tid & 31;
    for (int i = wid; i < cnt - 1; i += 8) {
        float2 a[8];
        #pragma unroll
        for (int q = 0; q < 8; q++) {
            half2 h = *(half2*)&sh[i * 256 + q * 32 + lane];
            a[q] = __half22float2(h);
        }
        const float sqi = s_sq[i];
        const int gi = s_idx[i];
        for (int j = i + 1; j < cnt; j++) {
            float p = 0.f;
            #pragma unroll
            for (int q = 0; q < 8; q++) {
                half2 h = *(half2*)&sh[j * 256 + q * 32 + lane];
                float2 b = __half22float2(h);
                p += a[q].x * b.x + a[q].y * b.y;
            }
            #pragma unroll
            for (int o = 16; o > 0; o >>= 1) p += __shfl_xor_sync(0xFFFFFFFF, p, o);
            if (lane == 0) {
                const float d2 = sqi + s_sq[j] - 2.f * p;
                if (d2 > 0.f) {
                    atomicMax((int*)&g_hp2[gi], __float_as_int(d2));
                    atomicMax((int*)&g_hp2[s_idx[j]], __float_as_int(d2));
                }
            }
        }
    }
}

// ---------------- mma / cp.async helpers ----------------
__device__ __forceinline__ void mma16(float* c, const uint32_t* a, const uint32_t* b) {
    asm volatile(
        "mma.sync.aligned.m16n8k16.row.col.f32.f16.f16.f32 "
        "{%0,%1,%2,%3},{%4,%5,%6,%7},{%8,%9},{%0,%1,%2,%3};"
        : "+f"(c[0]), "+f"(c[1]), "+f"(c[2]), "+f"(c[3])
        : "r"(a[0]), "r"(a[1]), "r"(a[2]), "r"(a[3]), "r"(b[0]), "r"(b[1]));
}
__device__ __forceinline__ void ldsm4(uint32_t& r0, uint32_t& r1, uint32_t& r2, uint32_t& r3,
                                      uint32_t addr) {
    asm volatile("ldmatrix.sync.aligned.m8n8.x4.shared.b16 {%0,%1,%2,%3}, [%4];"
                 : "=r"(r0), "=r"(r1), "=r"(r2), "=r"(r3) : "r"(addr));
}
__device__ __forceinline__ void cpa16(uint32_t dst, const void* src) {
    asm volatile("cp.async.cg.shared.global [%0], [%1], 16;" :: "r"(dst), "l"(src));
}
__device__ __forceinline__ void cpa_commit() {
    asm volatile("cp.async.commit_group;" ::: "memory");
}
template <int N>
__device__ __forceinline__ void cpa_wait() {
    asm volatile("cp.async.wait_group %0;" :: "n"(N) : "memory");
}

#define HSTRIDE 40                       // halfs per row (80 B)
#define BUFB (128 * HSTRIDE * 2)         // bytes per buffer = 10240

// ---------------- fp16 mma GEMM (upper triangle) + fused epilogue ----------------
__global__ void __launch_bounds__(256, 2) gemm_mma(const int* __restrict__ labels) {
    __shared__ __align__(16) half Abuf[2][128 * HSTRIDE];
    __shared__ __align__(16) half Bbuf[2][128 * HSTRIDE];
    __shared__ int s_rall[128], s_rsem[128], s_call[128], s_csem[128];
    __shared__ float s_sqi[128], s_sqj[128], s_hp2i[128], s_hp2j[128];
    __shared__ int s_li[128], s_lj[128];

    int rem = blockIdx.x, by = 0;
    while (rem >= TILES - by) { rem -= TILES - by; by++; }
    const int bx = by + rem;
    const bool diag = (bx == by);
    const int rowBase = by * 128;
    const int colBase = bx * 128;

    const int tid = threadIdx.x;
    const int wid = tid >> 5;
    const int lane = tid & 31;
    const int g = lane >> 2;
    const int t = lane & 3;
    const int mBase = (wid >> 2) * 64;
    const int nBase = (wid & 3) * 32;

    if (tid < 128) {
        s_rall[tid] = 0x7F800000; s_rsem[tid] = 0x7F800000;
        s_call[tid] = 0x7F800000; s_csem[tid] = 0x7F800000;
        const int gi = rowBase + tid, gj = colBase + tid;
        s_sqi[tid] = g_sq[gi]; s_hp2i[tid] = g_hp2[gi]; s_li[tid] = labels[gi];
        s_sqj[tid] = g_sq[gj]; s_hp2j[tid] = g_hp2[gj]; s_lj[tid] = labels[gj];
    }

    float acc[4][4][4];
    #pragma unroll
    for (int mf = 0; mf < 4; mf++)
        #pragma unroll
        for (int nf = 0; nf < 4; nf++)
            #pragma unroll
            for (int r = 0; r < 4; r++) acc[mf][nf][r] = 0.f;

    // cp.async producer mapping: 512 16B segments per operand, 2 per thread.
    const int prow = tid >> 2;          // 0..63
    const int pseg = tid & 3;           // 0..3
    const uint32_t Ash0 = (uint32_t)__cvta_generic_to_shared(&Abuf[0][0]);
    const uint32_t Bsh0 = (uint32_t)__cvta_generic_to_shared(&Bbuf[0][0]);
    const half* srcA = g_embh + (size_t)(rowBase + prow) * DDIM + pseg * 8;
    const half* srcB = g_embh + (size_t)(colBase + prow) * DDIM + pseg * 8;
    const uint32_t dstOff = prow * 80 + pseg * 16;

    // ldmatrix per-lane base addresses (buffer 0)
    const int arow = (lane & 7) + (((lane >> 3) & 1) << 3);
    const int acol = (lane >> 4) << 3;
    const int brow = ((lane >> 4) << 3) + (lane & 7);
    const int bcol = ((lane >> 3) & 1) << 3;
    const uint32_t aBase0 = Ash0 + (((mBase + arow) * HSTRIDE + acol) << 1);
    const uint32_t bBase0 = (diag ? Ash0 : Bsh0) + (((nBase + brow) * HSTRIDE + bcol) << 1);

    // issue chunk c loads
    auto issue = [&](int c) {
        const int buf = c & 1;
        const int k0 = c * 32;
        #pragma unroll
        for (int q = 0; q < 2; q++) {
            const int r = prow + q * 64;
            cpa16(Ash0 + buf * BUFB + dstOff + q * 64 * 80, srcA + (size_t)(q * 64) * DDIM + k0);
            if (!diag)
                cpa16(Bsh0 + buf * BUFB + dstOff + q * 64 * 80, srcB + (size_t)(q * 64) * DDIM + k0);
            (void)r;
        }
        cpa_commit();
    };

    issue(0);
    for (int c = 0; c < 16; c++) {
        const int buf = c & 1;
        if (c + 1 < 16) { issue(c + 1); cpa_wait<1>(); }
        else            { cpa_wait<0>(); }
        __syncthreads();

        #pragma unroll
        for (int s = 0; s < 2; s++) {
            uint32_t bf[4][2];
            #pragma unroll
            for (int q = 0; q < 2; q++) {
                const uint32_t baddr = bBase0 + buf * BUFB + ((q * 16 * HSTRIDE + s * 16) << 1);
                ldsm4(bf[2 * q][0], bf[2 * q][1], bf[2 * q + 1][0], bf[2 * q + 1][1], baddr);
            }
            #pragma unroll
            for (int mf = 0; mf < 4; mf++) {
                uint32_t af[4];
                const uint32_t aaddr = aBase0 + buf * BUFB + ((mf * 16 * HSTRIDE + s * 16) << 1);
                ldsm4(af[0], af[1], af[2], af[3], aaddr);
                #pragma unroll
                for (int nf = 0; nf < 4; nf++)
                    mma16(acc[mf][nf], af, bf[nf]);
            }
        }
        __syncthreads();
    }

    // ---------------- epilogue ----------------
    float rAll[4][2], rSem[4][2], cAll[4][2], cSem[4][2];
    #pragma unroll
    for (int x = 0; x < 4; x++)
        #pragma unroll
        for (int y = 0; y < 2; y++) {
            rAll[x][y] = CUDART_INF_F; rSem[x][y] = CUDART_INF_F;
            cAll[x][y] = CUDART_INF_F; cSem[x][y] = CUDART_INF_F;
        }

    #pragma unroll
    for (int mf = 0; mf < 4; mf++) {
        #pragma unroll
        for (int h = 0; h < 2; h++) {
            const int rloc = mBase + mf * 16 + g + 8 * h;
            const float sqi = s_sqi[rloc];
            const int li = s_li[rloc];
            const float hp2i = s_hp2i[rloc];
            #pragma unroll
            for (int nf = 0; nf < 4; nf++) {
                #pragma unroll
                for (int b = 0; b < 2; b++) {
                    const int cloc = nBase + nf * 8 + 2 * t + b;
                    const float dot = acc[mf][nf][2 * h + b];
                    const float v = fmaxf(sqi + s_sqj[cloc] - 2.f * dot, 0.f);
                    const bool neg = (li != s_lj[cloc]);
                    const float va = neg ? v : CUDART_INF_F;
                    const float vsr = (neg && v > hp2i) ? v : CUDART_INF_F;
                    const float vsc = (neg && v > s_hp2j[cloc]) ? v : CUDART_INF_F;
                    rAll[mf][h] = fminf(rAll[mf][h], va);
                    rSem[mf][h] = fminf(rSem[mf][h], vsr);
                    cAll[nf][b] = fminf(cAll[nf][b], va);
                    cSem[nf][b] = fminf(cSem[nf][b], vsc);
                }
            }
        }
    }

    #pragma unroll
    for (int mf = 0; mf < 4; mf++)
        #pragma unroll
        for (int h = 0; h < 2; h++) {
            float a = rAll[mf][h], s = rSem[mf][h];
            #pragma unroll
            for (int o = 1; o < 4; o <<= 1) {
                a = fminf(a, __shfl_xor_sync(0xFFFFFFFF, a, o));
                s = fminf(s, __shfl_xor_sync(0xFFFFFFFF, s, o));
            }
            if (t == 0) {
                const int rloc = mBase + mf * 16 + g + 8 * h;
                atomicMin(&s_rall[rloc], __float_as_int(a));
                atomicMin(&s_rsem[rloc], __float_as_int(s));
            }
        }
    #pragma unroll
    for (int nf = 0; nf < 4; nf++)
        #pragma unroll
        for (int b = 0; b < 2; b++) {
            float a = cAll[nf][b], s = cSem[nf][b];
            #pragma unroll
            for (int o = 4; o < 32; o <<= 1) {
                a = fminf(a, __shfl_xor_sync(0xFFFFFFFF, a, o));
                s = fminf(s, __shfl_xor_sync(0xFFFFFFFF, s, o));
            }
            if (g == 0) {
                const int cloc = nBase + nf * 8 + 2 * t + b;
                atomicMin(&s_call[cloc], __float_as_int(a));
                atomicMin(&s_csem[cloc], __float_as_int(s));
            }
        }
    __syncthreads();

    if (tid < 128) {
        g_all2[(size_t)bx * BDIM + rowBase + tid] = __int_as_float(s_rall[tid]);
        g_semi2[(size_t)bx * BDIM + rowBase + tid] = __int_as_float(s_rsem[tid]);
        if (!diag) {
            g_all2[(size_t)by * BDIM + colBase + tid] = __int_as_float(s_call[tid]);
            g_semi2[(size_t)by * BDIM + colBase + tid] = __int_as_float(s_csem[tid]);
        }
    }
}

// ---------------- per-row finish ----------------
__global__ void __launch_bounds__(256) rowfinish() {
    const int r = blockIdx.x * 256 + threadIdx.x;
    float mA = CUDART_INF_F, mS = CUDART_INF_F;
    #pragma unroll 8
    for (int tt = 0; tt < TILES; tt++) {
        mA = fminf(mA, g_all2[(size_t)tt * BDIM + r]);
        mS = fminf(mS, g_semi2[(size_t)tt * BDIM + r]);
    }
    const float hn2 = (mS < CUDART_INF_F) ? mS : mA;
    const float hp2 = g_hp2[r];
    float loss = 0.f;
    if (hp2 >= 0.f) {
        const float l = sqrtf(hp2) - sqrtf(hn2) + MARGIN;
        loss = fmaxf(l, 0.f);
    }
    g_loss[r] = loss;
}

__global__ void __launch_bounds__(256) final_reduce(float* __restrict__ out) {
    const int tid = threadIdx.x;
    float acc = 0.f;
    for (int k = tid; k < BDIM; k += 256) acc += g_loss[k];
    __shared__ float s[256];
    s[tid] = acc;
    __syncthreads();
    #pragma unroll
    for (int st = 128; st > 0; st >>= 1) {
        if (tid < st) s[tid] += s[tid + st];
        __syncthreads();
    }
    if (tid == 0) out[0] = s[0] / (float)BDIM;
}

// ---------------- launch ----------------
extern "C" void kernel_launch(void* const* d_in, const int* in_sizes, int n_in,
                              void* d_out, int out_size) {
    const float* emb = (const float*)d_in[0];
    const int* labels = (const int*)d_in[1];
    float* out = (float*)d_out;

    cudaFuncSetAttribute(hp_kernel, cudaFuncAttributeMaxDynamicSharedMemorySize, HPBYTES);

    prep_kernel<<<BDIM, 128>>>(emb);
    scatter_cls<<<BDIM / 256, 256>>>(labels);
    hp_kernel<<<512, 256, HPBYTES>>>();
    gemm_mma<<<NTRI, 256>>>(labels);
    rowfinish<<<BDIM / 256, 256>>>();
    final_reduce<<<1, 256>>>(out);
}

// round 10
// speedup vs baseline: 8.9549x; 1.0368x over previous
#include <cuda_runtime.h>
#include <cuda_fp16.h>
#include <math_constants.h>
#include <cstdint>

#define BDIM 8192
#define DDIM 512
#define MARGIN 0.2f
#define TILES 64
#define NTRI  (TILES * (TILES + 1) / 2)
#define HPMAXM 64
#define HPBYTES (HPMAXM * DDIM * 2)

// ---------------- scratch ----------------
__device__ __align__(16) half g_embh[(size_t)BDIM * DDIM];   // fp16 embeddings (8 MB)
__device__ float g_sq[BDIM];
__device__ float g_hp2[BDIM];
__device__ float g_all2[TILES * BDIM];
__device__ float g_semi2[TILES * BDIM];
__device__ float g_loss[BDIM];
__device__ int   g_ccnt[512];
__device__ int   g_cidx[512 * BDIM];

__device__ __forceinline__ uint32_t pack_h2(float x, float y) {
    half2 h = __floats2half2_rn(x, y);
    return *reinterpret_cast<uint32_t*>(&h);
}

// ---------------- prep: fp16 convert + sqnorm + init ----------------
__global__ void __launch_bounds__(128) prep_kernel(const float* __restrict__ emb) {
    const int i = blockIdx.x;
    const int tid = threadIdx.x;
    if (i < 4) g_ccnt[i * 128 + tid] = 0;
    if (tid == 0) g_hp2[i] = -CUDART_INF_F;
    float4 v = ((const float4*)(emb + (size_t)i * DDIM))[tid];
    ((uint2*)(g_embh + (size_t)i * DDIM))[tid] =
        make_uint2(pack_h2(v.x, v.y), pack_h2(v.z, v.w));
    float s = v.x * v.x + v.y * v.y + v.z * v.z + v.w * v.w;
    #pragma unroll
    for (int o = 16; o > 0; o >>= 1) s += __shfl_down_sync(0xFFFFFFFF, s, o);
    __shared__ float ws[4];
    if ((tid & 31) == 0) ws[tid >> 5] = s;
    __syncthreads();
    if (tid == 0) g_sq[i] = ws[0] + ws[1] + ws[2] + ws[3];
}

__global__ void scatter_cls(const int* __restrict__ labels) {
    int i = blockIdx.x * blockDim.x + threadIdx.x;
    if (i < BDIM) {
        int c = labels[i];
        int s = atomicAdd(&g_ccnt[c], 1);
        g_cidx[c * BDIM + s] = i;
    }
}

// ---------------- hardest positive: one block per class, 2-way j ILP ----------------
__global__ void __launch_bounds__(256) hp_kernel() {
    extern __shared__ uint32_t sh[];   // [m][256] half2 words
    __shared__ int s_idx[HPMAXM];
    __shared__ float s_sq[HPMAXM];

    const int c = blockIdx.x;
    const int cnt = min(g_ccnt[c], HPMAXM);
    const int tid = threadIdx.x;

    for (int m = tid; m < cnt; m += 256) {
        const int gi = g_cidx[c * BDIM + m];
        s_idx[m] = gi;
        s_sq[m] = g_sq[gi];
    }
    __syncthreads();
    for (int idx = tid; idx < cnt * 64; idx += 256) {
        const int m = idx >> 6, f = idx & 63;
        uint4 v = ((const uint4*)(g_embh + (size_t)s_idx[m] * DDIM))[f];
        *(uint4*)&sh[m * 256 + f * 4] = v;
    }
    __syncthreads();

    const int wid = tid >> 5, lane = tid & 31;
    for (int i = wid; i < cnt - 1; i += 8) {
        float2 a[8];
        #pragma unroll
        for (int q = 0; q < 8; q++) {
            half2 h = *(half2*)&sh[i * 256 + q * 32 + lane];
            a[q] = __half22float2(h);
        }
        const float sqi = s_sq[i];
        const int gi = s_idx[i];
        for (int j = i + 1; j < cnt; j += 2) {
            const bool has2 = (j + 1 < cnt);
            const int j1 = has2 ? j + 1 : j;
            float p0 = 0.f, p1 = 0.f;
            #pragma unroll
            for (int q = 0; q < 8; q++) {
                float2 b0 = __half22float2(*(half2*)&sh[j * 256 + q * 32 + lane]);
                float2 b1 = __half22float2(*(half2*)&sh[j1 * 256 + q * 32 + lane]);
                p0 += a[q].x * b0.x + a[q].y * b0.y;
                p1 += a[q].x * b1.x + a[q].y * b1.y;
            }
            #pragma unroll
            for (int o = 16; o > 0; o >>= 1) {
                p0 += __shfl_xor_sync(0xFFFFFFFF, p0, o);
                p1 += __shfl_xor_sync(0xFFFFFFFF, p1, o);
            }
            if (lane == 0) {
                const float d20 = sqi + s_sq[j] - 2.f * p0;
                if (d20 > 0.f) {
                    atomicMax((int*)&g_hp2[gi], __float_as_int(d20));
                    atomicMax((int*)&g_hp2[s_idx[j]], __float_as_int(d20));
                }
                if (has2) {
                    const float d21 = sqi + s_sq[j1] - 2.f * p1;
                    if (d21 > 0.f) {
                        atomicMax((int*)&g_hp2[gi], __float_as_int(d21));
                        atomicMax((int*)&g_hp2[s_idx[j1]], __float_as_int(d21));
                    }
                }
            }
        }
    }
}

// ---------------- mma / cp.async helpers ----------------
__device__ __forceinline__ void mma16(float* c, const uint32_t* a, const uint32_t* b) {
    asm volatile(
        "mma.sync.aligned.m16n8k16.row.col.f32.f16.f16.f32 "
        "{%0,%1,%2,%3},{%4,%5,%6,%7},{%8,%9},{%0,%1,%2,%3};"
        : "+f"(c[0]), "+f"(c[1]), "+f"(c[2]), "+f"(c[3])
        : "r"(a[0]), "r"(a[1]), "r"(a[2]), "r"(a[3]), "r"(b[0]), "r"(b[1]));
}
__device__ __forceinline__ void ldsm4(uint32_t& r0, uint32_t& r1, uint32_t& r2, uint32_t& r3,
                                      uint32_t addr) {
    asm volatile("ldmatrix.sync.aligned.m8n8.x4.shared.b16 {%0,%1,%2,%3}, [%4];"
                 : "=r"(r0), "=r"(r1), "=r"(r2), "=r"(r3) : "r"(addr));
}
__device__ __forceinline__ void cpa16(uint32_t dst, const void* src) {
    asm volatile("cp.async.cg.shared.global [%0], [%1], 16;" :: "r"(dst), "l"(src));
}
__device__ __forceinline__ void cpa_commit() {
    asm volatile("cp.async.commit_group;" ::: "memory");
}
template <int N>
__device__ __forceinline__ void cpa_wait() {
    asm volatile("cp.async.wait_group %0;" :: "n"(N) : "memory");
}

#define HSTRIDE 40                       // halfs per row (80 B)
#define BUFB (128 * HSTRIDE * 2)         // bytes per stage buffer = 10240
#define NSTAGE 4
#define GEMM_DYN (2 * NSTAGE * BUFB)     // A stages + B stages = 81920 bytes

// ---------------- fp16 mma GEMM: 4-stage pipeline + fused epilogue ----------------
__global__ void __launch_bounds__(256, 2) gemm_mma(const int* __restrict__ labels) {
    extern __shared__ __align__(16) char dynsm[];
    __shared__ int s_rall[128], s_rsem[128], s_call[128], s_csem[128];
    __shared__ float s_sqi[128], s_sqj[128], s_hp2i[128], s_hp2j[128];
    __shared__ int s_li[128], s_lj[128];

    int rem = blockIdx.x, by = 0;
    while (rem >= TILES - by) { rem -= TILES - by; by++; }
    const int bx = by + rem;
    const bool diag = (bx == by);
    const int rowBase = by * 128;
    const int colBase = bx * 128;

    const int tid = threadIdx.x;
    const int wid = tid >> 5;
    const int lane = tid & 31;
    const int g = lane >> 2;
    const int t = lane & 3;
    const int mBase = (wid >> 2) * 64;
    const int nBase = (wid & 3) * 32;

    if (tid < 128) {
        s_rall[tid] = 0x7F800000; s_rsem[tid] = 0x7F800000;
        s_call[tid] = 0x7F800000; s_csem[tid] = 0x7F800000;
        const int gi = rowBase + tid, gj = colBase + tid;
        s_sqi[tid] = g_sq[gi]; s_hp2i[tid] = g_hp2[gi]; s_li[tid] = labels[gi];
        s_sqj[tid] = g_sq[gj]; s_hp2j[tid] = g_hp2[gj]; s_lj[tid] = labels[gj];
    }

    float acc[4][4][4];
    #pragma unroll
    for (int mf = 0; mf < 4; mf++)
        #pragma unroll
        for (int nf = 0; nf < 4; nf++)
            #pragma unroll
            for (int r = 0; r < 4; r++) acc[mf][nf][r] = 0.f;

    // producer mapping: 512 16B segments per operand per chunk, 2 per thread
    const int prow = tid >> 2;
    const int pseg = tid & 3;
    const uint32_t AshD = (uint32_t)__cvta_generic_to_shared(dynsm);
    const uint32_t BshD = AshD + NSTAGE * BUFB;
    const half* srcA = g_embh + (size_t)(rowBase + prow) * DDIM + pseg * 8;
    const half* srcB = g_embh + (size_t)(colBase + prow) * DDIM + pseg * 8;
    const uint32_t dstOff = prow * 80 + pseg * 16;

    // ldmatrix per-lane base addresses (stage 0)
    const int arow = (lane & 7) + (((lane >> 3) & 1) << 3);
    const int acol = (lane >> 4) << 3;
    const int brow = ((lane >> 4) << 3) + (lane & 7);
    const int bcol = ((lane >> 3) & 1) << 3;
    const uint32_t aBase0 = AshD + (((mBase + arow) * HSTRIDE + acol) << 1);
    const uint32_t bBase0 = (diag ? AshD : BshD) + (((nBase + brow) * HSTRIDE + bcol) << 1);

    auto issue = [&](int c) {
        const int st = c & (NSTAGE - 1);
        const int k0 = c * 32;
        #pragma unroll
        for (int q = 0; q < 2; q++) {
            cpa16(AshD + st * BUFB + dstOff + q * 64 * 80, srcA + (size_t)(q * 64) * DDIM + k0);
            if (!diag)
                cpa16(BshD + st * BUFB + dstOff + q * 64 * 80, srcB + (size_t)(q * 64) * DDIM + k0);
        }
        cpa_commit();
    };

    issue(0); issue(1); issue(2);

    for (int c = 0; c < 16; c++) {
        if (c < 14)       cpa_wait<2>();
        else if (c == 14) cpa_wait<1>();
        else              cpa_wait<0>();
        __syncthreads();              // stage c visible; all warps done with chunk c-1
        if (c + 3 < 16) issue(c + 3); // overwrites stage (c-1)&3: safe after barrier

        const int st = c & (NSTAGE - 1);
        #pragma unroll
        for (int s = 0; s < 2; s++) {
            uint32_t bf[4][2];
            #pragma unroll
            for (int q = 0; q < 2; q++) {
                const uint32_t baddr = bBase0 + st * BUFB + ((q * 16 * HSTRIDE + s * 16) << 1);
                ldsm4(bf[2 * q][0], bf[2 * q][1], bf[2 * q + 1][0], bf[2 * q + 1][1], baddr);
            }
            #pragma unroll
            for (int mf = 0; mf < 4; mf++) {
                uint32_t af[4];
                const uint32_t aaddr = aBase0 + st * BUFB + ((mf * 16 * HSTRIDE + s * 16) << 1);
                ldsm4(af[0], af[1], af[2], af[3], aaddr);
                #pragma unroll
                for (int nf = 0; nf < 4; nf++)
                    mma16(acc[mf][nf], af, bf[nf]);
            }
        }
    }

    // ---------------- epilogue ----------------
    float rAll[4][2], rSem[4][2], cAll[4][2], cSem[4][2];
    #pragma unroll
    for (int x = 0; x < 4; x++)
        #pragma unroll
        for (int y = 0; y < 2; y++) {
            rAll[x][y] = CUDART_INF_F; rSem[x][y] = CUDART_INF_F;
            cAll[x][y] = CUDART_INF_F; cSem[x][y] = CUDART_INF_F;
        }

    #pragma unroll
    for (int mf = 0; mf < 4; mf++) {
        #pragma unroll
        for (int h = 0; h < 2; h++) {
            const int rloc = mBase + mf * 16 + g + 8 * h;
            const float sqi = s_sqi[rloc];
            const int li = s_li[rloc];
            const float hp2i = s_hp2i[rloc];
            #pragma unroll
            for (int nf = 0; nf < 4; nf++) {
                #pragma unroll
                for (int b = 0; b < 2; b++) {
                    const int cloc = nBase + nf * 8 + 2 * t + b;
                    const float dot = acc[mf][nf][2 * h + b];
                    const float v = fmaxf(sqi + s_sqj[cloc] - 2.f * dot, 0.f);
                    const bool neg = (li != s_lj[cloc]);
                    const float va = neg ? v : CUDART_INF_F;
                    const float vsr = (neg && v > hp2i) ? v : CUDART_INF_F;
                    const float vsc = (neg && v > s_hp2j[cloc]) ? v : CUDART_INF_F;
                    rAll[mf][h] = fminf(rAll[mf][h], va);
                    rSem[mf][h] = fminf(rSem[mf][h], vsr);
                    cAll[nf][b] = fminf(cAll[nf][b], va);
                    cSem[nf][b] = fminf(cSem[nf][b], vsc);
                }
            }
        }
    }

    #pragma unroll
    for (int mf = 0; mf < 4; mf++)
        #pragma unroll
        for (int h = 0; h < 2; h++) {
            float a = rAll[mf][h], s = rSem[mf][h];
            #pragma unroll
            for (int o = 1; o < 4; o <<= 1) {
                a = fminf(a, __shfl_xor_sync(0xFFFFFFFF, a, o));
                s = fminf(s, __shfl_xor_sync(0xFFFFFFFF, s, o));
            }
            if (t == 0) {
                const int rloc = mBase + mf * 16 + g + 8 * h;
                atomicMin(&s_rall[rloc], __float_as_int(a));
                atomicMin(&s_rsem[rloc], __float_as_int(s));
            }
        }
    #pragma unroll
    for (int nf = 0; nf < 4; nf++)
        #pragma unroll
        for (int b = 0; b < 2; b++) {
            float a = cAll[nf][b], s = cSem[nf][b];
            #pragma unroll
            for (int o = 4; o < 32; o <<= 1) {
                a = fminf(a, __shfl_xor_sync(0xFFFFFFFF, a, o));
                s = fminf(s, __shfl_xor_sync(0xFFFFFFFF, s, o));
            }
            if (g == 0) {
                const int cloc = nBase + nf * 8 + 2 * t + b;
                atomicMin(&s_call[cloc], __float_as_int(a));
                atomicMin(&s_csem[cloc], __float_as_int(s));
            }
        }
    __syncthreads();

    if (tid < 128) {
        g_all2[(size_t)bx * BDIM + rowBase + tid] = __int_as_float(s_rall[tid]);
        g_semi2[(size_t)bx * BDIM + rowBase + tid] = __int_as_float(s_rsem[tid]);
        if (!diag) {
            g_all2[(size_t)by * BDIM + colBase + tid] = __int_as_float(s_call[tid]);
            g_semi2[(size_t)by * BDIM + colBase + tid] = __int_as_float(s_csem[tid]);
        }
    }
}

// ---------------- per-row finish ----------------
__global__ void __launch_bounds__(256) rowfinish() {
    const int r = blockIdx.x * 256 + threadIdx.x;
    float mA = CUDART_INF_F, mS = CUDART_INF_F;
    #pragma unroll 8
    for (int tt = 0; tt < TILES; tt++) {
        mA = fminf(mA, g_all2[(size_t)tt * BDIM + r]);
        mS = fminf(mS, g_semi2[(size_t)tt * BDIM + r]);
    }
    const float hn2 = (mS < CUDART_INF_F) ? mS : mA;
    const float hp2 = g_hp2[r];
    float loss = 0.f;
    if (hp2 >= 0.f) {
        const float l = sqrtf(hp2) - sqrtf(hn2) + MARGIN;
        loss = fmaxf(l, 0.f);
    }
    g_loss[r] = loss;
}

__global__ void __launch_bounds__(256) final_reduce(float* __restrict__ out) {
    const int tid = threadIdx.x;
    float acc = 0.f;
    for (int k = tid; k < BDIM; k += 256) acc += g_loss[k];
    __shared__ float s[256];
    s[tid] = acc;
    __syncthreads();
    #pragma unroll
    for (int st = 128; st > 0; st >>= 1) {
        if (tid < st) s[tid] += s[tid + st];
        __syncthreads();
    }
    if (tid == 0) out[0] = s[0] / (float)BDIM;
}

// ---------------- launch ----------------
extern "C" void kernel_launch(void* const* d_in, const int* in_sizes, int n_in,
                              void* d_out, int out_size) {
    const float* emb = (const float*)d_in[0];
    const int* labels = (const int*)d_in[1];
    float* out = (float*)d_out;

    cudaFuncSetAttribute(hp_kernel, cudaFuncAttributeMaxDynamicSharedMemorySize, HPBYTES);
    cudaFuncSetAttribute(gemm_mma, cudaFuncAttributeMaxDynamicSharedMemorySize, GEMM_DYN);

    prep_kernel<<<BDIM, 128>>>(emb);
    scatter_cls<<<BDIM / 256, 256>>>(labels);
    hp_kernel<<<512, 256, HPBYTES>>>();
    gemm_mma<<<NTRI, 256, GEMM_DYN>>>(labels);
    rowfinish<<<BDIM / 256, 256>>>();
    final_reduce<<<1, 256>>>(out);
}